// round 1
// baseline (speedup 1.0000x reference)
#include <cuda_runtime.h>
#include <math.h>

#define SQ   4096
#define EMB  300
#define NH   3
#define HDIM 100
#define NHID 200

// ---------------- scratch (static device globals; no allocation) ----------------
__device__ float g_x[2 * SQ * EMB];      // encoder states (H at e=0, G at e=1)
__device__ float g_qkv[SQ * 3 * EMB];    // [S,900]
__device__ float g_o[SQ * EMB];          // attention output
__device__ float g_t1[SQ * EMB];         // proj / ff2 temp
__device__ float g_ff[SQ * NHID];        // ff1 output
__device__ float g_A[SQ * SQ];           // co-attention matrix (64 MB)
__device__ float g_P[SQ * EMB];
__device__ float g_Q[SQ * EMB];
__device__ float g_suv[2 * EMB];         // [sum(u,axis0), sum(v,axis0)]
__device__ float g_fc1o[EMB];

// ---------------- positional encoding + add ----------------
__global__ void add_pe_kernel(const float* __restrict__ src, float* __restrict__ x) {
    int idx = blockIdx.x * blockDim.x + threadIdx.x;
    if (idx >= SQ * EMB) return;
    int s = idx / EMB, c = idx % EMB;
    int k = c >> 1;
    float dv = expf(-(float)(2 * k) * (logf(10000.0f) / (float)EMB));
    float arg = (float)s * dv;
    float pe = (c & 1) ? cosf(arg) : sinf(arg);
    x[idx] = src[idx] + pe;
}

// ---------------- generic tiled fp32 GEMM ----------------
// C[m,n] = act( sum_k Ae(m,k)*Be(k,n) + bias[n] ),  ldc = N
// Ae(m,k) = TA ? A[k*lda+m] : A[m*lda+k];  Be(k,n) = TB ? B[n*ldb+k] : B[k*ldb+n]
template<int TA, int TB, int RELU>
__global__ void gemm_kernel(const float* __restrict__ A, const float* __restrict__ B,
                            const float* __restrict__ bias, float* __restrict__ C,
                            int M, int N, int K, int lda, int ldb) {
    __shared__ float As[16][64];
    __shared__ float Bs[16][64];
    int t = threadIdx.x;
    int tx = t & 15, ty = t >> 4;
    int row0 = blockIdx.y * 64, col0 = blockIdx.x * 64;
    float acc[4][4] = {};

    for (int kt = 0; kt < K; kt += 16) {
        if (!TA) {
            int m = t >> 2;
            int kq = (t & 3) << 2;
#pragma unroll
            for (int u = 0; u < 4; u++) {
                int k = kq + u;
                int gm = row0 + m, gk = kt + k;
                As[k][m] = (gm < M && gk < K) ? A[(size_t)gm * lda + gk] : 0.f;
            }
        } else {
            int k = t >> 4;
            int mq = (t & 15) << 2;
#pragma unroll
            for (int u = 0; u < 4; u++) {
                int m = mq + u;
                int gm = row0 + m, gk = kt + k;
                As[k][m] = (gm < M && gk < K) ? A[(size_t)gk * lda + gm] : 0.f;
            }
        }
        if (!TB) {
            int k = t >> 4;
            int nq = (t & 15) << 2;
#pragma unroll
            for (int u = 0; u < 4; u++) {
                int n = nq + u;
                int gk = kt + k, gn = col0 + n;
                Bs[k][n] = (gk < K && gn < N) ? B[(size_t)gk * ldb + gn] : 0.f;
            }
        } else {
            int n = t >> 2;
            int kq = (t & 3) << 2;
#pragma unroll
            for (int u = 0; u < 4; u++) {
                int k = kq + u;
                int gk = kt + k, gn = col0 + n;
                Bs[k][n] = (gk < K && gn < N) ? B[(size_t)gn * ldb + gk] : 0.f;
            }
        }
        __syncthreads();
#pragma unroll
        for (int k = 0; k < 16; k++) {
            float4 a4 = *(const float4*)&As[k][ty * 4];
            float4 b4 = *(const float4*)&Bs[k][tx * 4];
            float av[4] = {a4.x, a4.y, a4.z, a4.w};
            float bv[4] = {b4.x, b4.y, b4.z, b4.w};
#pragma unroll
            for (int i = 0; i < 4; i++)
#pragma unroll
                for (int j = 0; j < 4; j++)
                    acc[i][j] += av[i] * bv[j];
        }
        __syncthreads();
    }
#pragma unroll
    for (int i = 0; i < 4; i++) {
        int gm = row0 + ty * 4 + i;
        if (gm >= M) continue;
#pragma unroll
        for (int j = 0; j < 4; j++) {
            int gn = col0 + tx * 4 + j;
            if (gn >= N) continue;
            float v = acc[i][j];
            if (bias) v += bias[gn];
            if (RELU) v = fmaxf(v, 0.f);
            C[(size_t)gm * N + gn] = v;
        }
    }
}

// ---------------- fused causal flash attention ----------------
// block = 256 threads = 128 queries x 2 half-dims; grid = (32, 3 heads)
__global__ void attn_kernel(const float* __restrict__ qkv, float* __restrict__ o) {
    constexpr int QB = 128, TJ = 32, HF = 50;
    __shared__ float k_s[TJ][HDIM];
    __shared__ float v_s[TJ][HDIM];
    int h = blockIdx.y;
    // heaviest blocks (largest q0) first to reduce causal-tail imbalance
    int q0 = ((int)gridDim.x - 1 - (int)blockIdx.x) * QB;
    int t = threadIdx.x;
    int qi = q0 + (t >> 1);
    int dbase = (t & 1) * HF;

    const float* qrow = qkv + (size_t)qi * 900 + h * HDIM + dbase;
    float qv[HF], ov[HF];
#pragma unroll
    for (int i = 0; i < HF; i++) { qv[i] = qrow[i] * 0.1f; ov[i] = 0.f; }
    float m = -INFINITY, l = 0.f;

    int jmax = q0 + QB;
    for (int jt = 0; jt < jmax; jt += TJ) {
        for (int idx = t; idx < TJ * HDIM; idx += 256) {
            int jj = idx / HDIM, d = idx % HDIM;
            const float* base = qkv + (size_t)(jt + jj) * 900 + h * HDIM;
            k_s[jj][d] = base[300 + d];
            v_s[jj][d] = base[600 + d];
        }
        __syncthreads();
#pragma unroll 1
        for (int jj = 0; jj < TJ; jj++) {
            int j = jt + jj;
            float sp = 0.f;
#pragma unroll
            for (int i = 0; i < HF; i++) sp += qv[i] * k_s[jj][dbase + i];
            float s = sp + __shfl_xor_sync(0xffffffffu, sp, 1);
            if (j <= qi) {
                if (s <= m) {
                    float p = __expf(s - m);
                    l += p;
#pragma unroll
                    for (int i = 0; i < HF; i++) ov[i] += p * v_s[jj][dbase + i];
                } else {
                    float sc = __expf(m - s);  // m=-inf first time -> 0, correct
                    l = l * sc + 1.f;
#pragma unroll
                    for (int i = 0; i < HF; i++) ov[i] = ov[i] * sc + v_s[jj][dbase + i];
                    m = s;
                }
            }
        }
        __syncthreads();
    }
    float inv = 1.f / l;
    float* orow = o + (size_t)qi * EMB + h * HDIM + dbase;
#pragma unroll
    for (int i = 0; i < HF; i++) orow[i] = ov[i] * inv;
}

// ---------------- fused residual + LayerNorm (in place on x) ----------------
__global__ void ln_kernel(float* __restrict__ x, const float* __restrict__ delta,
                          const float* __restrict__ g, const float* __restrict__ b) {
    __shared__ float r1[128], r2[128];
    int r = blockIdx.x, t = threadIdx.x;
    float y[3];
    float s1 = 0.f, s2 = 0.f;
#pragma unroll
    for (int i = 0; i < 3; i++) {
        int c = t + i * 128;
        float v = 0.f;
        if (c < EMB) v = x[(size_t)r * EMB + c] + delta[(size_t)r * EMB + c];
        y[i] = v; s1 += v; s2 += v * v;
    }
    r1[t] = s1; r2[t] = s2;
    __syncthreads();
    for (int off = 64; off > 0; off >>= 1) {
        if (t < off) { r1[t] += r1[t + off]; r2[t] += r2[t + off]; }
        __syncthreads();
    }
    float mu = r1[0] / (float)EMB;
    float var = r2[0] / (float)EMB - mu * mu;
    float rstd = rsqrtf(var + 1e-5f);
#pragma unroll
    for (int i = 0; i < 3; i++) {
        int c = t + i * 128;
        if (c < EMB) x[(size_t)r * EMB + c] = (y[i] - mu) * rstd * g[c] + b[c];
    }
}

// ---------------- row softmax over A (in place) ----------------
__global__ void softmax_rows(float* __restrict__ A) {
    __shared__ float row[SQ];
    __shared__ float red[256];
    int r = blockIdx.x, t = threadIdx.x;
    float mx = -INFINITY;
    for (int j = t; j < SQ; j += 256) { float v = A[(size_t)r * SQ + j]; row[j] = v; mx = fmaxf(mx, v); }
    red[t] = mx; __syncthreads();
    for (int off = 128; off > 0; off >>= 1) { if (t < off) red[t] = fmaxf(red[t], red[t + off]); __syncthreads(); }
    mx = red[0];
    __syncthreads();
    float s = 0.f;
    for (int j = t; j < SQ; j += 256) { float e = __expf(row[j] - mx); row[j] = e; s += e; }
    red[t] = s; __syncthreads();
    for (int off = 128; off > 0; off >>= 1) { if (t < off) red[t] += red[t + off]; __syncthreads(); }
    float inv = 1.f / red[0];
    for (int j = t; j < SQ; j += 256) A[(size_t)r * SQ + j] = row[j] * inv;
}

// ---------------- column sum of elementwise max (deterministic) ----------------
__global__ void colsum_max_kernel(const float* __restrict__ X, const float* __restrict__ Y,
                                  float* __restrict__ out) {
    __shared__ float red[256];
    int c = blockIdx.x, t = threadIdx.x;
    float s = 0.f;
    for (int r = t; r < SQ; r += 256)
        s += fmaxf(X[(size_t)r * EMB + c], Y[(size_t)r * EMB + c]);
    red[t] = s; __syncthreads();
    for (int off = 128; off > 0; off >>= 1) { if (t < off) red[t] += red[t + off]; __syncthreads(); }
    if (t == 0) out[c] = red[0];
}

// ---------------- tiny FC layers ----------------
__global__ void fc1_kernel(const float* __restrict__ inp, const float* __restrict__ w,
                           const float* __restrict__ b, float* __restrict__ out) {
    __shared__ float red[128];
    int i = blockIdx.x, t = threadIdx.x;
    float s = 0.f;
    for (int j = t; j < 2 * EMB; j += 128) s += inp[j] * w[(size_t)i * 2 * EMB + j];
    red[t] = s; __syncthreads();
    for (int off = 64; off > 0; off >>= 1) { if (t < off) red[t] += red[t + off]; __syncthreads(); }
    if (t == 0) out[i] = fmaxf(red[0] + b[i], 0.f);
}

__global__ void fc2_kernel(const float* __restrict__ inp, const float* __restrict__ w,
                           const float* __restrict__ b, float* __restrict__ out) {
    __shared__ float red[256];
    int t = threadIdx.x;
    float s = 0.f;
    for (int j = t; j < EMB; j += 256) s += inp[j] * w[j];
    red[t] = s; __syncthreads();
    for (int off = 128; off > 0; off >>= 1) { if (t < off) red[t] += red[t + off]; __syncthreads(); }
    if (t == 0) out[0] = red[0] + b[0];
}

// ---------------- host orchestration ----------------
static inline dim3 gemm_grid(int M, int N) { return dim3((N + 63) / 64, (M + 63) / 64); }

extern "C" void kernel_launch(void* const* d_in, const int* in_sizes, int n_in,
                              void* d_out, int out_size) {
    const float* solv = (const float*)d_in[0];
    const float* solu = (const float*)d_in[1];
    const float* ipw  = (const float*)d_in[2];   // [2,900,300]
    const float* ipb  = (const float*)d_in[3];   // [2,900]
    const float* ow   = (const float*)d_in[4];   // [2,300,300]
    const float* ob   = (const float*)d_in[5];
    const float* g1   = (const float*)d_in[6];
    const float* b1   = (const float*)d_in[7];
    const float* w1   = (const float*)d_in[8];   // [2,200,300]
    const float* bb1  = (const float*)d_in[9];
    const float* w2   = (const float*)d_in[10];  // [2,300,200]
    const float* bb2  = (const float*)d_in[11];
    const float* g2   = (const float*)d_in[12];
    const float* b2   = (const float*)d_in[13];
    const float* fc1w = (const float*)d_in[14];  // [300,600]
    const float* fc1b = (const float*)d_in[15];
    const float* fc2w = (const float*)d_in[16];  // [1,300]
    const float* fc2b = (const float*)d_in[17];

    float *x, *qkv, *o, *t1, *ff, *A, *P, *Q, *suv, *fc1o;
    cudaGetSymbolAddress((void**)&x,    g_x);
    cudaGetSymbolAddress((void**)&qkv,  g_qkv);
    cudaGetSymbolAddress((void**)&o,    g_o);
    cudaGetSymbolAddress((void**)&t1,   g_t1);
    cudaGetSymbolAddress((void**)&ff,   g_ff);
    cudaGetSymbolAddress((void**)&A,    g_A);
    cudaGetSymbolAddress((void**)&P,    g_P);
    cudaGetSymbolAddress((void**)&Q,    g_Q);
    cudaGetSymbolAddress((void**)&suv,  g_suv);
    cudaGetSymbolAddress((void**)&fc1o, g_fc1o);

    for (int e = 0; e < 2; e++) {
        float* xe = x + (size_t)e * SQ * EMB;
        add_pe_kernel<<<(SQ * EMB + 255) / 256, 256>>>(e ? solu : solv, xe);

        // qkv = xe @ ipw_e^T + ipb_e   [4096,900]
        gemm_kernel<0, 1, 0><<<gemm_grid(SQ, 3 * EMB), 256>>>(
            xe, ipw + (size_t)e * 3 * EMB * EMB, ipb + (size_t)e * 3 * EMB, qkv,
            SQ, 3 * EMB, EMB, EMB, EMB);

        attn_kernel<<<dim3(SQ / 128, NH), 256>>>(qkv, o);

        // proj = o @ ow_e^T + ob_e
        gemm_kernel<0, 1, 0><<<gemm_grid(SQ, EMB), 256>>>(
            o, ow + (size_t)e * EMB * EMB, ob + (size_t)e * EMB, t1,
            SQ, EMB, EMB, EMB, EMB);
        ln_kernel<<<SQ, 128>>>(xe, t1, g1 + e * EMB, b1 + e * EMB);

        // ff1 = relu(xe @ w1^T + bb1)   [4096,200]
        gemm_kernel<0, 1, 1><<<gemm_grid(SQ, NHID), 256>>>(
            xe, w1 + (size_t)e * NHID * EMB, bb1 + (size_t)e * NHID, ff,
            SQ, NHID, EMB, EMB, EMB);
        // ff2 = ff1 @ w2^T + bb2   [4096,300]
        gemm_kernel<0, 1, 0><<<gemm_grid(SQ, EMB), 256>>>(
            ff, w2 + (size_t)e * EMB * NHID, bb2 + (size_t)e * EMB, t1,
            SQ, EMB, NHID, NHID, NHID);
        ln_kernel<<<SQ, 128>>>(xe, t1, g2 + e * EMB, b2 + e * EMB);
    }

    float* H = x;
    float* G = x + (size_t)SQ * EMB;

    // A = H @ G^T   [4096,4096]
    gemm_kernel<0, 1, 0><<<gemm_grid(SQ, SQ), 256>>>(
        H, G, (const float*)nullptr, A, SQ, SQ, EMB, EMB, EMB);
    softmax_rows<<<SQ, 256>>>(A);

    // P = A @ G   (NN), Q = A^T @ H   (TN)
    gemm_kernel<0, 0, 0><<<gemm_grid(SQ, EMB), 256>>>(
        A, G, (const float*)nullptr, P, SQ, EMB, SQ, SQ, EMB);
    gemm_kernel<1, 0, 0><<<gemm_grid(SQ, EMB), 256>>>(
        A, H, (const float*)nullptr, Q, SQ, EMB, SQ, SQ, EMB);

    colsum_max_kernel<<<EMB, 256>>>(H, P, suv);
    colsum_max_kernel<<<EMB, 256>>>(G, Q, suv + EMB);

    fc1_kernel<<<EMB, 128>>>(suv, fc1w, fc1b, fc1o);
    fc2_kernel<<<1, 256>>>(fc1o, fc2w, fc2b, (float*)d_out);
}

// round 2
// speedup vs baseline: 1.6045x; 1.6045x over previous
#include <cuda_runtime.h>
#include <math.h>

#define SQ   4096
#define EMB  300
#define NH   3
#define HDIM 100
#define NHID 200
#define QB   64
#define TJ   32
#define JCH  1024
#define NCH  4

// ---------------- scratch (static device globals; no allocation) ----------------
__device__ float g_x[2 * SQ * EMB];          // encoder states (H at e=0, G at e=1)
__device__ float g_qkv[2 * SQ * 3 * EMB];    // [2,S,900]
__device__ float g_o[2 * SQ * EMB];          // attention output
__device__ float g_t1[2 * SQ * EMB];         // proj / ff2 temp
__device__ float g_ff[2 * SQ * NHID];        // ff1 output
__device__ float g_A[SQ * SQ];               // co-attention matrix (64 MB)
__device__ float g_P[SQ * EMB];
__device__ float g_Q[SQ * EMB];
__device__ float g_Pp[NCH * SQ * EMB];       // split-K partials
__device__ float g_Qp[NCH * SQ * EMB];
__device__ float g_part_o[6 * NCH * SQ * HDIM];   // attention partials (unnormalized)
__device__ float g_part_ml[6 * NCH * SQ * 2];     // (m, l) per partial
__device__ float g_suv[2 * EMB];
__device__ float g_fc1o[EMB];

// ---------------- positional encoding + add (batched over z=encoder) ----------------
__global__ void add_pe_kernel(const float* __restrict__ solv, const float* __restrict__ solu,
                              float* __restrict__ x) {
    int idx = blockIdx.x * blockDim.x + threadIdx.x;
    if (idx >= SQ * EMB) return;
    int z = blockIdx.z;
    const float* src = z ? solu : solv;
    int s = idx / EMB, c = idx % EMB;
    int k = c >> 1;
    float dv = expf(-(float)(2 * k) * (logf(10000.0f) / (float)EMB));
    float arg = (float)s * dv;
    float pe = (c & 1) ? cosf(arg) : sinf(arg);
    x[(size_t)z * SQ * EMB + idx] = src[idx] + pe;
}

// ---------------- tiled fp32 GEMM: 128x64x16, 8x4 microtile, batched / split-K ----------------
// C[m,n] = act( sum_k Ae(m,k)*Be(k,n) + bias[n] ),  ldc = N
// Ae(m,k) = TA ? A[k*lda+m] : A[m*lda+k];  Be(k,n) = TB ? B[n*ldb+k] : B[k*ldb+n]
// SPLITK: blockIdx.z selects k-range [z*kc, min(K,(z+1)*kc)), C += z*sC (sC = M*N), no bias.
// else:   blockIdx.z is batch index; A/B/bias/C offset by strides.
template<int TA, int TB, int RELU, int SPLITK>
__global__ __launch_bounds__(256, 2)
void gemm2(const float* __restrict__ A, const float* __restrict__ B,
           const float* __restrict__ bias, float* __restrict__ C,
           int M, int N, int K, int lda, int ldb,
           size_t sA, size_t sB, size_t sBias, size_t sC, int kc) {
    int z = blockIdx.z;
    int k_begin = 0, k_end = K;
    if (SPLITK) {
        k_begin = z * kc;
        k_end = min(K, k_begin + kc);
        C += (size_t)z * sC;
    } else {
        A += (size_t)z * sA; B += (size_t)z * sB; C += (size_t)z * sC;
        if (bias) bias += (size_t)z * sBias;
    }

    __shared__ float As[16][128];
    __shared__ float Bs[16][64];
    int t = threadIdx.x;
    int tx = t & 15, ty = t >> 4;
    int row0 = blockIdx.y * 128, col0 = blockIdx.x * 64;
    float acc[8][4] = {};
    float ra[8], rb[4];

    int nk = (k_end - k_begin + 15) >> 4;

    auto loadA = [&](int kt) {
#pragma unroll
        for (int u = 0; u < 8; u++) {
            int m, k;
            if (!TA) { m = t >> 1; k = ((t & 1) << 3) + u; }
            else     { k = t >> 4; m = ((t & 15) << 3) + u; }
            int gm = row0 + m, gk = kt + k;
            bool ok = (gm < M) && (gk < k_end);
            ra[u] = ok ? (TA ? A[(size_t)gk * lda + gm] : A[(size_t)gm * lda + gk]) : 0.f;
        }
    };
    auto loadB = [&](int kt) {
#pragma unroll
        for (int u = 0; u < 4; u++) {
            int k, n;
            if (!TB) { k = t >> 4; n = ((t & 15) << 2) + u; }
            else     { n = t >> 2; k = ((t & 3) << 2) + u; }
            int gn = col0 + n, gk = kt + k;
            bool ok = (gn < N) && (gk < k_end);
            rb[u] = ok ? (TB ? B[(size_t)gn * ldb + gk] : B[(size_t)gk * ldb + gn]) : 0.f;
        }
    };

    loadA(k_begin); loadB(k_begin);
    for (int it = 0; it < nk; it++) {
        __syncthreads();
#pragma unroll
        for (int u = 0; u < 8; u++) {
            if (!TA) As[((t & 1) << 3) + u][t >> 1] = ra[u];
            else     As[t >> 4][((t & 15) << 3) + u] = ra[u];
        }
#pragma unroll
        for (int u = 0; u < 4; u++) {
            if (!TB) Bs[t >> 4][((t & 15) << 2) + u] = rb[u];
            else     Bs[((t & 3) << 2) + u][t >> 2] = rb[u];
        }
        __syncthreads();
        if (it + 1 < nk) { loadA(k_begin + (it + 1) * 16); loadB(k_begin + (it + 1) * 16); }
#pragma unroll
        for (int k = 0; k < 16; k++) {
            float4 a0 = *(const float4*)&As[k][ty << 2];
            float4 a1 = *(const float4*)&As[k][64 + (ty << 2)];
            float4 b  = *(const float4*)&Bs[k][tx << 2];
            float av[8] = {a0.x, a0.y, a0.z, a0.w, a1.x, a1.y, a1.z, a1.w};
            float bv[4] = {b.x, b.y, b.z, b.w};
#pragma unroll
            for (int i = 0; i < 8; i++)
#pragma unroll
                for (int j = 0; j < 4; j++)
                    acc[i][j] += av[i] * bv[j];
        }
    }

#pragma unroll
    for (int h = 0; h < 2; h++) {
#pragma unroll
        for (int i = 0; i < 4; i++) {
            int gm = row0 + h * 64 + (ty << 2) + i;
            if (gm >= M) continue;
            int gn0 = col0 + (tx << 2);
            float v0 = acc[h * 4 + i][0], v1 = acc[h * 4 + i][1];
            float v2 = acc[h * 4 + i][2], v3 = acc[h * 4 + i][3];
            if (!SPLITK && bias) {
                if (gn0 + 3 < N) { v0 += bias[gn0]; v1 += bias[gn0+1]; v2 += bias[gn0+2]; v3 += bias[gn0+3]; }
                else { if (gn0 < N) v0 += bias[gn0]; if (gn0+1 < N) v1 += bias[gn0+1];
                       if (gn0+2 < N) v2 += bias[gn0+2]; if (gn0+3 < N) v3 += bias[gn0+3]; }
            }
            if (RELU) { v0 = fmaxf(v0, 0.f); v1 = fmaxf(v1, 0.f); v2 = fmaxf(v2, 0.f); v3 = fmaxf(v3, 0.f); }
            if (gn0 + 3 < N) {
                float4 out = {v0, v1, v2, v3};
                *(float4*)&C[(size_t)gm * N + gn0] = out;
            } else {
                if (gn0 < N)     C[(size_t)gm * N + gn0]     = v0;
                if (gn0 + 1 < N) C[(size_t)gm * N + gn0 + 1] = v1;
                if (gn0 + 2 < N) C[(size_t)gm * N + gn0 + 2] = v2;
                if (gn0 + 3 < N) C[(size_t)gm * N + gn0 + 3] = v3;
            }
        }
    }
}

// ---------------- split-K reduce for P and Q ----------------
__global__ void reduce_pq(const float* __restrict__ Pp, const float* __restrict__ Qp,
                          float* __restrict__ P, float* __restrict__ Q) {
    int idx = blockIdx.x * 256 + threadIdx.x;
    if (idx >= SQ * EMB) return;
    const float* src = blockIdx.y ? Qp : Pp;
    float* dst = blockIdx.y ? Q : P;
    float s = 0.f;
#pragma unroll
    for (int c = 0; c < NCH; c++) s += src[(size_t)c * SQ * EMB + idx];
    dst[idx] = s;
}

// ---------------- flash attention, j-chunked (partials) ----------------
// grid: (64 q-tiles, NCH chunks, 6 = enc*3+head); block: 128 = 64 queries x 2 halves
__global__ void attn_kernel(const float* __restrict__ qkv_all,
                            float* __restrict__ part_o, float* __restrict__ part_ml) {
    __shared__ float k_s[TJ][HDIM];
    __shared__ float v_s[TJ][HDIM];
    int z = blockIdx.z;
    int e = z / 3, h = z % 3;
    int qt = (int)gridDim.x - 1 - (int)blockIdx.x;  // heaviest first
    int q0 = qt * QB;
    int c = blockIdx.y;
    int c0 = c * JCH;
    if (c0 > q0 + QB - 1) return;

    const float* qkv = qkv_all + (size_t)e * SQ * 900;
    int t = threadIdx.x;
    int qi = q0 + (t >> 1);
    int dbase = (t & 1) * 50;

    const float* qrow = qkv + (size_t)qi * 900 + h * HDIM + dbase;
    float qv[50], ov[50];
#pragma unroll
    for (int i = 0; i < 50; i++) { qv[i] = qrow[i] * 0.1f; ov[i] = 0.f; }
    float m = -INFINITY, l = 0.f;

    int jend = min(c0 + JCH, q0 + QB);
    for (int jt = c0; jt < jend; jt += TJ) {
        __syncthreads();
        for (int idx = t; idx < TJ * HDIM; idx += 128) {
            int jj = idx / HDIM, d = idx % HDIM;
            const float* base = qkv + (size_t)(jt + jj) * 900 + h * HDIM + d;
            k_s[jj][d] = base[300];
            v_s[jj][d] = base[600];
        }
        __syncthreads();
#pragma unroll 1
        for (int jj = 0; jj < TJ; jj++) {
            int j = jt + jj;
            float sp = 0.f;
            const float* kr = &k_s[jj][dbase];
#pragma unroll
            for (int i = 0; i < 50; i++) sp += qv[i] * kr[i];
            float s = sp + __shfl_xor_sync(0xffffffffu, sp, 1);
            if (j <= qi) {
                const float* vr = &v_s[jj][dbase];
                if (s <= m) {
                    float p = __expf(s - m);
                    l += p;
#pragma unroll
                    for (int i = 0; i < 50; i++) ov[i] += p * vr[i];
                } else {
                    float sc = __expf(m - s);  // m=-inf first time -> 0, correct
                    l = l * sc + 1.f;
#pragma unroll
                    for (int i = 0; i < 50; i++) ov[i] = ov[i] * sc + vr[i];
                    m = s;
                }
            }
        }
    }

    size_t pbase = (size_t)(z * NCH + c) * SQ + qi;
    float* po = part_o + pbase * HDIM + dbase;
#pragma unroll
    for (int i = 0; i < 50; i++) po[i] = ov[i];
    if ((t & 1) == 0) {
        part_ml[pbase * 2]     = m;
        part_ml[pbase * 2 + 1] = l;
    }
}

// combine partials: grid (4096, 3, 2), 128 threads (100 active)
__global__ void attn_combine(const float* __restrict__ part_o,
                             const float* __restrict__ part_ml,
                             float* __restrict__ o_all) {
    int qi = blockIdx.x, h = blockIdx.y, e = blockIdx.z;
    int z = e * 3 + h;
    int t = threadIdx.x;
    int nch = qi / JCH + 1;
    float M = -INFINITY;
    for (int cc = 0; cc < nch; cc++)
        M = fmaxf(M, part_ml[((size_t)(z * NCH + cc) * SQ + qi) * 2]);
    float L = 0.f, acc = 0.f;
    for (int cc = 0; cc < nch; cc++) {
        size_t pb = (size_t)(z * NCH + cc) * SQ + qi;
        float w = __expf(part_ml[pb * 2] - M);
        L += part_ml[pb * 2 + 1] * w;
        if (t < HDIM) acc += w * part_o[pb * HDIM + t];
    }
    if (t < HDIM)
        o_all[((size_t)e * SQ + qi) * EMB + h * HDIM + t] = acc / L;
}

// ---------------- fused residual + LayerNorm (in place, batched over z) ----------------
__global__ void ln_kernel(float* __restrict__ x, const float* __restrict__ delta,
                          const float* __restrict__ g, const float* __restrict__ b) {
    __shared__ float r1[128], r2[128];
    int z = blockIdx.z;
    x += (size_t)z * SQ * EMB; delta += (size_t)z * SQ * EMB;
    g += z * EMB; b += z * EMB;
    int r = blockIdx.x, t = threadIdx.x;
    float y[3];
    float s1 = 0.f, s2 = 0.f;
#pragma unroll
    for (int i = 0; i < 3; i++) {
        int c = t + i * 128;
        float v = 0.f;
        if (c < EMB) v = x[(size_t)r * EMB + c] + delta[(size_t)r * EMB + c];
        y[i] = v; s1 += v; s2 += v * v;
    }
    r1[t] = s1; r2[t] = s2;
    __syncthreads();
    for (int off = 64; off > 0; off >>= 1) {
        if (t < off) { r1[t] += r1[t + off]; r2[t] += r2[t + off]; }
        __syncthreads();
    }
    float mu = r1[0] / (float)EMB;
    float var = r2[0] / (float)EMB - mu * mu;
    float rstd = rsqrtf(var + 1e-5f);
#pragma unroll
    for (int i = 0; i < 3; i++) {
        int c = t + i * 128;
        if (c < EMB) x[(size_t)r * EMB + c] = (y[i] - mu) * rstd * g[c] + b[c];
    }
}

// ---------------- row softmax over A (in place) ----------------
__global__ void softmax_rows(float* __restrict__ A) {
    __shared__ float row[SQ];
    __shared__ float red[256];
    int r = blockIdx.x, t = threadIdx.x;
    float mx = -INFINITY;
    for (int j = t; j < SQ; j += 256) { float v = A[(size_t)r * SQ + j]; row[j] = v; mx = fmaxf(mx, v); }
    red[t] = mx; __syncthreads();
    for (int off = 128; off > 0; off >>= 1) { if (t < off) red[t] = fmaxf(red[t], red[t + off]); __syncthreads(); }
    mx = red[0];
    __syncthreads();
    float s = 0.f;
    for (int j = t; j < SQ; j += 256) { float e = __expf(row[j] - mx); row[j] = e; s += e; }
    red[t] = s; __syncthreads();
    for (int off = 128; off > 0; off >>= 1) { if (t < off) red[t] += red[t + off]; __syncthreads(); }
    float inv = 1.f / red[0];
    for (int j = t; j < SQ; j += 256) A[(size_t)r * SQ + j] = row[j] * inv;
}

// ---------------- column sum of elementwise max (deterministic) ----------------
__global__ void colsum_max_kernel(const float* __restrict__ X, const float* __restrict__ Y,
                                  float* __restrict__ out) {
    __shared__ float red[256];
    int c = blockIdx.x, t = threadIdx.x;
    float s = 0.f;
    for (int r = t; r < SQ; r += 256)
        s += fmaxf(X[(size_t)r * EMB + c], Y[(size_t)r * EMB + c]);
    red[t] = s; __syncthreads();
    for (int off = 128; off > 0; off >>= 1) { if (t < off) red[t] += red[t + off]; __syncthreads(); }
    if (t == 0) out[c] = red[0];
}

// ---------------- tiny FC layers ----------------
__global__ void fc1_kernel(const float* __restrict__ inp, const float* __restrict__ w,
                           const float* __restrict__ b, float* __restrict__ out) {
    __shared__ float red[128];
    int i = blockIdx.x, t = threadIdx.x;
    float s = 0.f;
    for (int j = t; j < 2 * EMB; j += 128) s += inp[j] * w[(size_t)i * 2 * EMB + j];
    red[t] = s; __syncthreads();
    for (int off = 64; off > 0; off >>= 1) { if (t < off) red[t] += red[t + off]; __syncthreads(); }
    if (t == 0) out[i] = fmaxf(red[0] + b[i], 0.f);
}

__global__ void fc2_kernel(const float* __restrict__ inp, const float* __restrict__ w,
                           const float* __restrict__ b, float* __restrict__ out) {
    __shared__ float red[256];
    int t = threadIdx.x;
    float s = 0.f;
    for (int j = t; j < EMB; j += 256) s += inp[j] * w[j];
    red[t] = s; __syncthreads();
    for (int off = 128; off > 0; off >>= 1) { if (t < off) red[t] += red[t + off]; __syncthreads(); }
    if (t == 0) out[0] = red[0] + b[0];
}

// ---------------- host orchestration ----------------
extern "C" void kernel_launch(void* const* d_in, const int* in_sizes, int n_in,
                              void* d_out, int out_size) {
    const float* solv = (const float*)d_in[0];
    const float* solu = (const float*)d_in[1];
    const float* ipw  = (const float*)d_in[2];   // [2,900,300]
    const float* ipb  = (const float*)d_in[3];   // [2,900]
    const float* ow   = (const float*)d_in[4];   // [2,300,300]
    const float* ob   = (const float*)d_in[5];
    const float* g1   = (const float*)d_in[6];
    const float* b1   = (const float*)d_in[7];
    const float* w1   = (const float*)d_in[8];   // [2,200,300]
    const float* bb1  = (const float*)d_in[9];
    const float* w2   = (const float*)d_in[10];  // [2,300,200]
    const float* bb2  = (const float*)d_in[11];
    const float* g2   = (const float*)d_in[12];
    const float* b2   = (const float*)d_in[13];
    const float* fc1w = (const float*)d_in[14];  // [300,600]
    const float* fc1b = (const float*)d_in[15];
    const float* fc2w = (const float*)d_in[16];  // [1,300]
    const float* fc2b = (const float*)d_in[17];

    float *x, *qkv, *o, *t1, *ff, *A, *P, *Q, *Pp, *Qp, *po, *pml, *suv, *fc1o;
    cudaGetSymbolAddress((void**)&x,    g_x);
    cudaGetSymbolAddress((void**)&qkv,  g_qkv);
    cudaGetSymbolAddress((void**)&o,    g_o);
    cudaGetSymbolAddress((void**)&t1,   g_t1);
    cudaGetSymbolAddress((void**)&ff,   g_ff);
    cudaGetSymbolAddress((void**)&A,    g_A);
    cudaGetSymbolAddress((void**)&P,    g_P);
    cudaGetSymbolAddress((void**)&Q,    g_Q);
    cudaGetSymbolAddress((void**)&Pp,   g_Pp);
    cudaGetSymbolAddress((void**)&Qp,   g_Qp);
    cudaGetSymbolAddress((void**)&po,   g_part_o);
    cudaGetSymbolAddress((void**)&pml,  g_part_ml);
    cudaGetSymbolAddress((void**)&suv,  g_suv);
    cudaGetSymbolAddress((void**)&fc1o, g_fc1o);

    const size_t SE = (size_t)SQ * EMB;

    // x = src + PE (both encoders)
    add_pe_kernel<<<dim3((SQ * EMB + 255) / 256, 1, 2), 256>>>(solv, solu, x);

    // qkv = x @ ipw^T + ipb   [2][4096,900]
    gemm2<0, 1, 0, 0><<<dim3(15, 32, 2), 256>>>(
        x, ipw, ipb, qkv, SQ, 3 * EMB, EMB, EMB, EMB,
        SE, (size_t)3 * EMB * EMB, 3 * EMB, (size_t)SQ * 3 * EMB, 0);

    // flash attention with j-chunks, both encoders, all heads
    attn_kernel<<<dim3(SQ / QB, NCH, 6), 128>>>(qkv, po, pml);
    attn_combine<<<dim3(SQ, NH, 2), 128>>>(po, pml, o);

    // proj = o @ ow^T + ob
    gemm2<0, 1, 0, 0><<<dim3(5, 32, 2), 256>>>(
        o, ow, ob, t1, SQ, EMB, EMB, EMB, EMB,
        SE, (size_t)EMB * EMB, EMB, SE, 0);
    ln_kernel<<<dim3(SQ, 1, 2), 128>>>(x, t1, g1, b1);

    // ff1 = relu(x @ w1^T + bb1)   [2][4096,200]
    gemm2<0, 1, 1, 0><<<dim3(4, 32, 2), 256>>>(
        x, w1, bb1, ff, SQ, NHID, EMB, EMB, EMB,
        SE, (size_t)NHID * EMB, NHID, (size_t)SQ * NHID, 0);
    // ff2 = ff1 @ w2^T + bb2
    gemm2<0, 1, 0, 0><<<dim3(5, 32, 2), 256>>>(
        ff, w2, bb2, t1, SQ, EMB, NHID, NHID, NHID,
        (size_t)SQ * NHID, (size_t)EMB * NHID, EMB, SE, 0);
    ln_kernel<<<dim3(SQ, 1, 2), 128>>>(x, t1, g2, b2);

    float* H = x;
    float* G = x + SE;

    // A = H @ G^T   [4096,4096]
    gemm2<0, 1, 0, 0><<<dim3(64, 32, 1), 256>>>(
        H, G, (const float*)nullptr, A, SQ, SQ, EMB, EMB, EMB, 0, 0, 0, 0, 0);
    softmax_rows<<<SQ, 256>>>(A);

    // P = A @ G (NN, split-K x4), Q = A^T @ H (TN, split-K x4)
    gemm2<0, 0, 0, 1><<<dim3(5, 32, NCH), 256>>>(
        A, G, (const float*)nullptr, Pp, SQ, EMB, SQ, SQ, EMB, 0, 0, 0, SE, JCH);
    gemm2<1, 0, 0, 1><<<dim3(5, 32, NCH), 256>>>(
        A, H, (const float*)nullptr, Qp, SQ, EMB, SQ, SQ, EMB, 0, 0, 0, SE, JCH);
    reduce_pq<<<dim3((SQ * EMB + 255) / 256, 2), 256>>>(Pp, Qp, P, Q);

    colsum_max_kernel<<<EMB, 256>>>(H, P, suv);
    colsum_max_kernel<<<EMB, 256>>>(G, Q, suv + EMB);

    fc1_kernel<<<EMB, 128>>>(suv, fc1w, fc1b, fc1o);
    fc2_kernel<<<1, 256>>>(fc1o, fc2w, fc2b, (float*)d_out);
}

// round 3
// speedup vs baseline: 1.8441x; 1.1493x over previous
#include <cuda_runtime.h>
#include <math.h>
#include <stdint.h>

#define SQ   4096
#define EMB  300
#define NH   3
#define HDIM 100
#define NHID 200
#define QB   64
#define TJ   32
#define JCH  1024
#define NCH  4
#define KC   32
#define PADA 4
#define PADB 4

// ---------------- scratch (static device globals; no allocation) ----------------
__device__ float g_x[2 * SQ * EMB];
__device__ float g_qkv[2 * SQ * 3 * EMB];
__device__ float g_o[2 * SQ * EMB];
__device__ float g_t1[2 * SQ * EMB];
__device__ float g_ff[2 * SQ * NHID];
__device__ float g_A[SQ * SQ];
__device__ float g_P[SQ * EMB];
__device__ float g_Q[SQ * EMB];
__device__ float g_Pp[NCH * SQ * EMB];
__device__ float g_Qp[NCH * SQ * EMB];
__device__ float g_part_o[6 * NCH * SQ * HDIM];
__device__ float g_part_ml[6 * NCH * SQ * 2];
__device__ float g_suv[2 * EMB];
__device__ float g_fc1o[EMB];

// ---------------- positional encoding + add ----------------
__global__ void add_pe_kernel(const float* __restrict__ solv, const float* __restrict__ solu,
                              float* __restrict__ x) {
    int idx = blockIdx.x * blockDim.x + threadIdx.x;
    if (idx >= SQ * EMB) return;
    int z = blockIdx.z;
    const float* src = z ? solu : solv;
    int s = idx / EMB, c = idx % EMB;
    int k = c >> 1;
    float dv = expf(-(float)(2 * k) * (logf(10000.0f) / (float)EMB));
    float arg = (float)s * dv;
    float pe = (c & 1) ? cosf(arg) : sinf(arg);
    x[(size_t)z * SQ * EMB + idx] = src[idx] + pe;
}

// ---------------- tf32 tensor-core GEMM ----------------
__device__ __forceinline__ uint32_t f2tf(float f) {
    uint32_t r;
    asm("cvt.rna.tf32.f32 %0, %1;" : "=r"(r) : "f"(f));
    return r;
}

// C[m,n] = act( sum_k Ae(m,k)*Be(k,n) + bias[n] ),  ldc = N
// Ae(m,k) = TA ? A[k*lda+m] : A[m*lda+k];  Be(k,n) = TB ? B[n*ldb+k] : B[k*ldb+n]
// SPLITK: z selects k-range [z*kc, ...), C += z*sC, no bias. else z = batch index.
template<int TA, int TB, int RELU, int SPLITK>
__global__ __launch_bounds__(256, 2)
void mma_gemm(const float* __restrict__ A, const float* __restrict__ B,
              const float* __restrict__ bias, float* __restrict__ C,
              int M, int N, int K, int lda, int ldb,
              size_t sA, size_t sB, size_t sBias, size_t sC, int kc) {
    int z = blockIdx.z;
    int k_begin = 0, k_end = K;
    if (SPLITK) {
        k_begin = z * kc;
        k_end = min(K, k_begin + kc);
        C += (size_t)z * sC;
    } else {
        A += (size_t)z * sA; B += (size_t)z * sB; C += (size_t)z * sC;
        if (bias) bias += (size_t)z * sBias;
    }

    __shared__ uint32_t As[KC][128 + PADA];
    __shared__ uint32_t Bs[KC][64 + PADB];

    int t = threadIdx.x;
    int warp = t >> 5, lane = t & 31;
    int g = lane >> 2, tig = lane & 3;
    int wm = warp & 3, wn = warp >> 2;   // 4 x 2 warp grid
    int row0 = blockIdx.y * 128, col0 = blockIdx.x * 64;
    int wr0 = wm * 32, wc0 = wn * 32;

    float c[2][4][4];
#pragma unroll
    for (int i = 0; i < 2; i++)
#pragma unroll
        for (int j = 0; j < 4; j++)
#pragma unroll
            for (int h = 0; h < 4; h++) c[i][j][h] = 0.f;

    for (int kt = k_begin; kt < k_end; kt += KC) {
        if (!TA) {
            int m = t >> 1, kq = (t & 1) * 16;
            int gm = row0 + m;
            const float* Ap = A + (size_t)gm * lda + kt + kq;
#pragma unroll
            for (int u = 0; u < 16; u++) {
                int gk = kt + kq + u;
                float v = (gm < M && gk < k_end) ? Ap[u] : 0.f;
                As[kq + u][m] = f2tf(v);
            }
        } else {
            int k = t >> 3, mq = (t & 7) * 16;
            int gk = kt + k;
            const float* Ap = A + (size_t)gk * lda + row0 + mq;
#pragma unroll
            for (int u = 0; u < 16; u++) {
                int gm = row0 + mq + u;
                float v = (gm < M && gk < k_end) ? Ap[u] : 0.f;
                As[k][mq + u] = f2tf(v);
            }
        }
        if (!TB) {
            int k = t >> 3, nq = (t & 7) * 8;
            int gk = kt + k;
            const float* Bp = B + (size_t)gk * ldb + col0 + nq;
#pragma unroll
            for (int u = 0; u < 8; u++) {
                int gn = col0 + nq + u;
                float v = (gn < N && gk < k_end) ? Bp[u] : 0.f;
                Bs[k][nq + u] = f2tf(v);
            }
        } else {
            int n = t >> 2, kq = (t & 3) * 8;
            int gn = col0 + n;
            const float* Bp = B + (size_t)gn * ldb + kt + kq;
#pragma unroll
            for (int u = 0; u < 8; u++) {
                int gk = kt + kq + u;
                float v = (gn < N && gk < k_end) ? Bp[u] : 0.f;
                Bs[kq + u][n] = f2tf(v);
            }
        }
        __syncthreads();
#pragma unroll
        for (int ks = 0; ks < KC; ks += 8) {
            uint32_t a[2][4], b[4][2];
#pragma unroll
            for (int i = 0; i < 2; i++) {
                int mb = wr0 + i * 16;
                a[i][0] = As[ks + tig][mb + g];
                a[i][1] = As[ks + tig][mb + 8 + g];
                a[i][2] = As[ks + tig + 4][mb + g];
                a[i][3] = As[ks + tig + 4][mb + 8 + g];
            }
#pragma unroll
            for (int j = 0; j < 4; j++) {
                int nb = wc0 + j * 8;
                b[j][0] = Bs[ks + tig][nb + g];
                b[j][1] = Bs[ks + tig + 4][nb + g];
            }
#pragma unroll
            for (int i = 0; i < 2; i++)
#pragma unroll
                for (int j = 0; j < 4; j++)
                    asm volatile(
                        "mma.sync.aligned.m16n8k8.row.col.f32.tf32.tf32.f32 "
                        "{%0,%1,%2,%3},{%4,%5,%6,%7},{%8,%9},{%0,%1,%2,%3};"
                        : "+f"(c[i][j][0]), "+f"(c[i][j][1]), "+f"(c[i][j][2]), "+f"(c[i][j][3])
                        : "r"(a[i][0]), "r"(a[i][1]), "r"(a[i][2]), "r"(a[i][3]),
                          "r"(b[j][0]), "r"(b[j][1]));
        }
        __syncthreads();
    }

#pragma unroll
    for (int i = 0; i < 2; i++) {
        int r0 = row0 + wr0 + i * 16 + g;
#pragma unroll
        for (int j = 0; j < 4; j++) {
            int cc = col0 + wc0 + j * 8 + tig * 2;
#pragma unroll
            for (int h = 0; h < 2; h++) {
                int gr = r0 + h * 8;
                if (gr >= M) continue;
                float v0 = c[i][j][h * 2], v1 = c[i][j][h * 2 + 1];
                if (!SPLITK && bias) {
                    if (cc < N) v0 += bias[cc];
                    if (cc + 1 < N) v1 += bias[cc + 1];
                }
                if (RELU) { v0 = fmaxf(v0, 0.f); v1 = fmaxf(v1, 0.f); }
                if (cc + 1 < N) {
                    *(float2*)&C[(size_t)gr * N + cc] = make_float2(v0, v1);
                } else if (cc < N) {
                    C[(size_t)gr * N + cc] = v0;
                }
            }
        }
    }
}

// ---------------- split-K reduce for P and Q ----------------
__global__ void reduce_pq(const float* __restrict__ Pp, const float* __restrict__ Qp,
                          float* __restrict__ P, float* __restrict__ Q) {
    int idx = blockIdx.x * 256 + threadIdx.x;
    if (idx >= SQ * EMB) return;
    const float* src = blockIdx.y ? Qp : Pp;
    float* dst = blockIdx.y ? Q : P;
    float s = 0.f;
#pragma unroll
    for (int c = 0; c < NCH; c++) s += src[(size_t)c * SQ * EMB + idx];
    dst[idx] = s;
}

// ---------------- flash attention, j-chunked (partials) ----------------
__global__ void attn_kernel(const float* __restrict__ qkv_all,
                            float* __restrict__ part_o, float* __restrict__ part_ml) {
    __shared__ float k_s[TJ][HDIM];
    __shared__ float v_s[TJ][HDIM];
    int z = blockIdx.z;
    int e = z / 3, h = z % 3;
    int qt = (int)gridDim.x - 1 - (int)blockIdx.x;  // heaviest first
    int q0 = qt * QB;
    int c = blockIdx.y;
    int c0 = c * JCH;
    if (c0 > q0 + QB - 1) return;

    const float* qkv = qkv_all + (size_t)e * SQ * 900;
    int t = threadIdx.x;
    int qi = q0 + (t >> 1);
    int dbase = (t & 1) * 50;

    const float* qrow = qkv + (size_t)qi * 900 + h * HDIM + dbase;
    float qv[50], ov[50];
#pragma unroll
    for (int i = 0; i < 50; i++) { qv[i] = qrow[i] * 0.1f; ov[i] = 0.f; }
    float m = -INFINITY, l = 0.f;

    int jend = min(c0 + JCH, q0 + QB);
    for (int jt = c0; jt < jend; jt += TJ) {
        __syncthreads();
        for (int idx = t; idx < TJ * HDIM; idx += 128) {
            int jj = idx / HDIM, d = idx % HDIM;
            const float* base = qkv + (size_t)(jt + jj) * 900 + h * HDIM + d;
            k_s[jj][d] = base[300];
            v_s[jj][d] = base[600];
        }
        __syncthreads();
#pragma unroll 1
        for (int jj = 0; jj < TJ; jj++) {
            int j = jt + jj;
            float sp = 0.f;
            const float2* kr2 = (const float2*)&k_s[jj][dbase];
#pragma unroll
            for (int i = 0; i < 25; i++) {
                float2 kk = kr2[i];
                sp += qv[2 * i] * kk.x + qv[2 * i + 1] * kk.y;
            }
            float s = sp + __shfl_xor_sync(0xffffffffu, sp, 1);
            if (j <= qi) {
                const float2* vr2 = (const float2*)&v_s[jj][dbase];
                if (s <= m) {
                    float p = __expf(s - m);
                    l += p;
#pragma unroll
                    for (int i = 0; i < 25; i++) {
                        float2 vv = vr2[i];
                        ov[2 * i] += p * vv.x;
                        ov[2 * i + 1] += p * vv.y;
                    }
                } else {
                    float sc = __expf(m - s);  // m=-inf first time -> 0, correct
                    l = l * sc + 1.f;
#pragma unroll
                    for (int i = 0; i < 25; i++) {
                        float2 vv = vr2[i];
                        ov[2 * i] = ov[2 * i] * sc + vv.x;
                        ov[2 * i + 1] = ov[2 * i + 1] * sc + vv.y;
                    }
                    m = s;
                }
            }
        }
    }

    size_t pbase = (size_t)(z * NCH + c) * SQ + qi;
    float* po = part_o + pbase * HDIM + dbase;
#pragma unroll
    for (int i = 0; i < 50; i++) po[i] = ov[i];
    if ((t & 1) == 0) {
        part_ml[pbase * 2]     = m;
        part_ml[pbase * 2 + 1] = l;
    }
}

__global__ void attn_combine(const float* __restrict__ part_o,
                             const float* __restrict__ part_ml,
                             float* __restrict__ o_all) {
    int qi = blockIdx.x, h = blockIdx.y, e = blockIdx.z;
    int z = e * 3 + h;
    int t = threadIdx.x;
    int nch = qi / JCH + 1;
    float M = -INFINITY;
    for (int cc = 0; cc < nch; cc++)
        M = fmaxf(M, part_ml[((size_t)(z * NCH + cc) * SQ + qi) * 2]);
    float L = 0.f, acc = 0.f;
    for (int cc = 0; cc < nch; cc++) {
        size_t pb = (size_t)(z * NCH + cc) * SQ + qi;
        float w = __expf(part_ml[pb * 2] - M);
        L += part_ml[pb * 2 + 1] * w;
        if (t < HDIM) acc += w * part_o[pb * HDIM + t];
    }
    if (t < HDIM)
        o_all[((size_t)e * SQ + qi) * EMB + h * HDIM + t] = acc / L;
}

// ---------------- fused residual + LayerNorm ----------------
__global__ void ln_kernel(float* __restrict__ x, const float* __restrict__ delta,
                          const float* __restrict__ g, const float* __restrict__ b) {
    __shared__ float r1[128], r2[128];
    int z = blockIdx.z;
    x += (size_t)z * SQ * EMB; delta += (size_t)z * SQ * EMB;
    g += z * EMB; b += z * EMB;
    int r = blockIdx.x, t = threadIdx.x;
    float y[3];
    float s1 = 0.f, s2 = 0.f;
#pragma unroll
    for (int i = 0; i < 3; i++) {
        int c = t + i * 128;
        float v = 0.f;
        if (c < EMB) v = x[(size_t)r * EMB + c] + delta[(size_t)r * EMB + c];
        y[i] = v; s1 += v; s2 += v * v;
    }
    r1[t] = s1; r2[t] = s2;
    __syncthreads();
    for (int off = 64; off > 0; off >>= 1) {
        if (t < off) { r1[t] += r1[t + off]; r2[t] += r2[t + off]; }
        __syncthreads();
    }
    float mu = r1[0] / (float)EMB;
    float var = r2[0] / (float)EMB - mu * mu;
    float rstd = rsqrtf(var + 1e-5f);
#pragma unroll
    for (int i = 0; i < 3; i++) {
        int c = t + i * 128;
        if (c < EMB) x[(size_t)r * EMB + c] = (y[i] - mu) * rstd * g[c] + b[c];
    }
}

// ---------------- row softmax over A (in place) ----------------
__global__ void softmax_rows(float* __restrict__ A) {
    __shared__ float row[SQ];
    __shared__ float red[256];
    int r = blockIdx.x, t = threadIdx.x;
    float mx = -INFINITY;
    for (int j = t; j < SQ; j += 256) { float v = A[(size_t)r * SQ + j]; row[j] = v; mx = fmaxf(mx, v); }
    red[t] = mx; __syncthreads();
    for (int off = 128; off > 0; off >>= 1) { if (t < off) red[t] = fmaxf(red[t], red[t + off]); __syncthreads(); }
    mx = red[0];
    __syncthreads();
    float s = 0.f;
    for (int j = t; j < SQ; j += 256) { float e = __expf(row[j] - mx); row[j] = e; s += e; }
    red[t] = s; __syncthreads();
    for (int off = 128; off > 0; off >>= 1) { if (t < off) red[t] += red[t + off]; __syncthreads(); }
    float inv = 1.f / red[0];
    for (int j = t; j < SQ; j += 256) A[(size_t)r * SQ + j] = row[j] * inv;
}

// ---------------- column sum of elementwise max ----------------
__global__ void colsum_max_kernel(const float* __restrict__ X, const float* __restrict__ Y,
                                  float* __restrict__ out) {
    __shared__ float red[256];
    int c = blockIdx.x, t = threadIdx.x;
    float s = 0.f;
    for (int r = t; r < SQ; r += 256)
        s += fmaxf(X[(size_t)r * EMB + c], Y[(size_t)r * EMB + c]);
    red[t] = s; __syncthreads();
    for (int off = 128; off > 0; off >>= 1) { if (t < off) red[t] += red[t + off]; __syncthreads(); }
    if (t == 0) out[c] = red[0];
}

// ---------------- tiny FC layers ----------------
__global__ void fc1_kernel(const float* __restrict__ inp, const float* __restrict__ w,
                           const float* __restrict__ b, float* __restrict__ out) {
    __shared__ float red[128];
    int i = blockIdx.x, t = threadIdx.x;
    float s = 0.f;
    for (int j = t; j < 2 * EMB; j += 128) s += inp[j] * w[(size_t)i * 2 * EMB + j];
    red[t] = s; __syncthreads();
    for (int off = 64; off > 0; off >>= 1) { if (t < off) red[t] += red[t + off]; __syncthreads(); }
    if (t == 0) out[i] = fmaxf(red[0] + b[i], 0.f);
}

__global__ void fc2_kernel(const float* __restrict__ inp, const float* __restrict__ w,
                           const float* __restrict__ b, float* __restrict__ out) {
    __shared__ float red[256];
    int t = threadIdx.x;
    float s = 0.f;
    for (int j = t; j < EMB; j += 256) s += inp[j] * w[j];
    red[t] = s; __syncthreads();
    for (int off = 128; off > 0; off >>= 1) { if (t < off) red[t] += red[t + off]; __syncthreads(); }
    if (t == 0) out[0] = red[0] + b[0];
}

// ---------------- host orchestration ----------------
extern "C" void kernel_launch(void* const* d_in, const int* in_sizes, int n_in,
                              void* d_out, int out_size) {
    const float* solv = (const float*)d_in[0];
    const float* solu = (const float*)d_in[1];
    const float* ipw  = (const float*)d_in[2];
    const float* ipb  = (const float*)d_in[3];
    const float* ow   = (const float*)d_in[4];
    const float* ob   = (const float*)d_in[5];
    const float* g1   = (const float*)d_in[6];
    const float* b1   = (const float*)d_in[7];
    const float* w1   = (const float*)d_in[8];
    const float* bb1  = (const float*)d_in[9];
    const float* w2   = (const float*)d_in[10];
    const float* bb2  = (const float*)d_in[11];
    const float* g2   = (const float*)d_in[12];
    const float* b2   = (const float*)d_in[13];
    const float* fc1w = (const float*)d_in[14];
    const float* fc1b = (const float*)d_in[15];
    const float* fc2w = (const float*)d_in[16];
    const float* fc2b = (const float*)d_in[17];

    float *x, *qkv, *o, *t1, *ff, *A, *P, *Q, *Pp, *Qp, *po, *pml, *suv, *fc1o;
    cudaGetSymbolAddress((void**)&x,    g_x);
    cudaGetSymbolAddress((void**)&qkv,  g_qkv);
    cudaGetSymbolAddress((void**)&o,    g_o);
    cudaGetSymbolAddress((void**)&t1,   g_t1);
    cudaGetSymbolAddress((void**)&ff,   g_ff);
    cudaGetSymbolAddress((void**)&A,    g_A);
    cudaGetSymbolAddress((void**)&P,    g_P);
    cudaGetSymbolAddress((void**)&Q,    g_Q);
    cudaGetSymbolAddress((void**)&Pp,   g_Pp);
    cudaGetSymbolAddress((void**)&Qp,   g_Qp);
    cudaGetSymbolAddress((void**)&po,   g_part_o);
    cudaGetSymbolAddress((void**)&pml,  g_part_ml);
    cudaGetSymbolAddress((void**)&suv,  g_suv);
    cudaGetSymbolAddress((void**)&fc1o, g_fc1o);

    const size_t SE = (size_t)SQ * EMB;

    add_pe_kernel<<<dim3((SQ * EMB + 255) / 256, 1, 2), 256>>>(solv, solu, x);

    // qkv = x @ ipw^T + ipb
    mma_gemm<0, 1, 0, 0><<<dim3(15, 32, 2), 256>>>(
        x, ipw, ipb, qkv, SQ, 3 * EMB, EMB, EMB, EMB,
        SE, (size_t)3 * EMB * EMB, 3 * EMB, (size_t)SQ * 3 * EMB, 0);

    attn_kernel<<<dim3(SQ / QB, NCH, 6), 128>>>(qkv, po, pml);
    attn_combine<<<dim3(SQ, NH, 2), 128>>>(po, pml, o);

    // proj = o @ ow^T + ob
    mma_gemm<0, 1, 0, 0><<<dim3(5, 32, 2), 256>>>(
        o, ow, ob, t1, SQ, EMB, EMB, EMB, EMB,
        SE, (size_t)EMB * EMB, EMB, SE, 0);
    ln_kernel<<<dim3(SQ, 1, 2), 128>>>(x, t1, g1, b1);

    // ff1 = relu(x @ w1^T + bb1)
    mma_gemm<0, 1, 1, 0><<<dim3(4, 32, 2), 256>>>(
        x, w1, bb1, ff, SQ, NHID, EMB, EMB, EMB,
        SE, (size_t)NHID * EMB, NHID, (size_t)SQ * NHID, 0);
    // ff2 = ff1 @ w2^T + bb2
    mma_gemm<0, 1, 0, 0><<<dim3(5, 32, 2), 256>>>(
        ff, w2, bb2, t1, SQ, EMB, NHID, NHID, NHID,
        (size_t)SQ * NHID, (size_t)EMB * NHID, EMB, SE, 0);
    ln_kernel<<<dim3(SQ, 1, 2), 128>>>(x, t1, g2, b2);

    float* H = x;
    float* G = x + SE;

    // A = H @ G^T
    mma_gemm<0, 1, 0, 0><<<dim3(64, 32, 1), 256>>>(
        H, G, (const float*)nullptr, A, SQ, SQ, EMB, EMB, EMB, 0, 0, 0, 0, 0);
    softmax_rows<<<SQ, 256>>>(A);

    // P = A @ G (NN, split-K x4), Q = A^T @ H (TN, split-K x4)
    mma_gemm<0, 0, 0, 1><<<dim3(5, 32, NCH), 256>>>(
        A, G, (const float*)nullptr, Pp, SQ, EMB, SQ, SQ, EMB, 0, 0, 0, SE, JCH);
    mma_gemm<1, 0, 0, 1><<<dim3(5, 32, NCH), 256>>>(
        A, H, (const float*)nullptr, Qp, SQ, EMB, SQ, SQ, EMB, 0, 0, 0, SE, JCH);
    reduce_pq<<<dim3((SQ * EMB + 255) / 256, 2), 256>>>(Pp, Qp, P, Q);

    colsum_max_kernel<<<EMB, 256>>>(H, P, suv);
    colsum_max_kernel<<<EMB, 256>>>(G, Q, suv + EMB);

    fc1_kernel<<<EMB, 128>>>(suv, fc1w, fc1b, fc1o);
    fc2_kernel<<<1, 256>>>(fc1o, fc2w, fc2b, (float*)d_out);
}

// round 4
// speedup vs baseline: 2.7738x; 1.5041x over previous
#include <cuda_runtime.h>
#include <math.h>
#include <stdint.h>

#define SQ   4096
#define EMB  300
#define NH   3
#define HDIM 100
#define NHID 200
#define QB   64
#define TJ   32
#define JCH  1024
#define NCH  4
#define KC   32
#define PADA 4
#define PADB 4

// ---------------- scratch (static device globals; no allocation) ----------------
__device__ float g_x[2 * SQ * EMB];
__device__ float g_qkv[2 * SQ * 3 * EMB];
__device__ float g_o[2 * SQ * EMB];
__device__ float g_t1[2 * SQ * EMB];
__device__ float g_ff[2 * SQ * NHID];
__device__ float g_A[SQ * SQ];
__device__ float g_P[SQ * EMB];
__device__ float g_Q[SQ * EMB];
__device__ float g_Pp[NCH * SQ * EMB];
__device__ float g_Qp[NCH * SQ * EMB];
__device__ float g_part_o[6 * NCH * SQ * HDIM];
__device__ float g_part_ml[6 * NCH * SQ * 2];
__device__ float g_suv[2 * EMB];
__device__ float g_fc1o[EMB];

// ---------------- positional encoding + add ----------------
__global__ void add_pe_kernel(const float* __restrict__ solv, const float* __restrict__ solu,
                              float* __restrict__ x) {
    int idx = blockIdx.x * blockDim.x + threadIdx.x;
    if (idx >= SQ * EMB) return;
    int z = blockIdx.z;
    const float* src = z ? solu : solv;
    int s = idx / EMB, c = idx % EMB;
    int k = c >> 1;
    float dv = expf(-(float)(2 * k) * (logf(10000.0f) / (float)EMB));
    float arg = (float)s * dv;
    float pe = (c & 1) ? cosf(arg) : sinf(arg);
    x[(size_t)z * SQ * EMB + idx] = src[idx] + pe;
}

// ---------------- tf32 helpers ----------------
__device__ __forceinline__ uint32_t f2tf(float f) {
    uint32_t r;
    asm("cvt.rna.tf32.f32 %0, %1;" : "=r"(r) : "f"(f));
    return r;
}

#define MMA_TF32(C, A, B0, B1)                                                  \
    asm volatile(                                                               \
        "mma.sync.aligned.m16n8k8.row.col.f32.tf32.tf32.f32 "                   \
        "{%0,%1,%2,%3},{%4,%5,%6,%7},{%8,%9},{%0,%1,%2,%3};"                    \
        : "+f"((C)[0]), "+f"((C)[1]), "+f"((C)[2]), "+f"((C)[3])                \
        : "r"((A)[0]), "r"((A)[1]), "r"((A)[2]), "r"((A)[3]), "r"(B0), "r"(B1))

// ---------------- tf32 tensor-core GEMM ----------------
template<int TA, int TB, int RELU, int SPLITK>
__global__ __launch_bounds__(256, 2)
void mma_gemm(const float* __restrict__ A, const float* __restrict__ B,
              const float* __restrict__ bias, float* __restrict__ C,
              int M, int N, int K, int lda, int ldb,
              size_t sA, size_t sB, size_t sBias, size_t sC, int kc) {
    int z = blockIdx.z;
    int k_begin = 0, k_end = K;
    if (SPLITK) {
        k_begin = z * kc;
        k_end = min(K, k_begin + kc);
        C += (size_t)z * sC;
    } else {
        A += (size_t)z * sA; B += (size_t)z * sB; C += (size_t)z * sC;
        if (bias) bias += (size_t)z * sBias;
    }

    __shared__ uint32_t As[KC][128 + PADA];
    __shared__ uint32_t Bs[KC][64 + PADB];

    int t = threadIdx.x;
    int warp = t >> 5, lane = t & 31;
    int g = lane >> 2, tig = lane & 3;
    int wm = warp & 3, wn = warp >> 2;
    int row0 = blockIdx.y * 128, col0 = blockIdx.x * 64;
    int wr0 = wm * 32, wc0 = wn * 32;

    float c[2][4][4];
#pragma unroll
    for (int i = 0; i < 2; i++)
#pragma unroll
        for (int j = 0; j < 4; j++)
#pragma unroll
            for (int h = 0; h < 4; h++) c[i][j][h] = 0.f;

    for (int kt = k_begin; kt < k_end; kt += KC) {
        if (!TA) {
            int m = t >> 1, kq = (t & 1) * 16;
            int gm = row0 + m;
            const float* Ap = A + (size_t)gm * lda + kt + kq;
#pragma unroll
            for (int u = 0; u < 16; u++) {
                int gk = kt + kq + u;
                float v = (gm < M && gk < k_end) ? Ap[u] : 0.f;
                As[kq + u][m] = f2tf(v);
            }
        } else {
            int k = t >> 3, mq = (t & 7) * 16;
            int gk = kt + k;
            const float* Ap = A + (size_t)gk * lda + row0 + mq;
#pragma unroll
            for (int u = 0; u < 16; u++) {
                int gm = row0 + mq + u;
                float v = (gm < M && gk < k_end) ? Ap[u] : 0.f;
                As[k][mq + u] = f2tf(v);
            }
        }
        if (!TB) {
            int k = t >> 3, nq = (t & 7) * 8;
            int gk = kt + k;
            const float* Bp = B + (size_t)gk * ldb + col0 + nq;
#pragma unroll
            for (int u = 0; u < 8; u++) {
                int gn = col0 + nq + u;
                float v = (gn < N && gk < k_end) ? Bp[u] : 0.f;
                Bs[k][nq + u] = f2tf(v);
            }
        } else {
            int n = t >> 2, kq = (t & 3) * 8;
            int gn = col0 + n;
            const float* Bp = B + (size_t)gn * ldb + kt + kq;
#pragma unroll
            for (int u = 0; u < 8; u++) {
                int gk = kt + kq + u;
                float v = (gn < N && gk < k_end) ? Bp[u] : 0.f;
                Bs[kq + u][n] = f2tf(v);
            }
        }
        __syncthreads();
#pragma unroll
        for (int ks = 0; ks < KC; ks += 8) {
            uint32_t a[2][4], b[4][2];
#pragma unroll
            for (int i = 0; i < 2; i++) {
                int mb = wr0 + i * 16;
                a[i][0] = As[ks + tig][mb + g];
                a[i][1] = As[ks + tig][mb + 8 + g];
                a[i][2] = As[ks + tig + 4][mb + g];
                a[i][3] = As[ks + tig + 4][mb + 8 + g];
            }
#pragma unroll
            for (int j = 0; j < 4; j++) {
                int nb = wc0 + j * 8;
                b[j][0] = Bs[ks + tig][nb + g];
                b[j][1] = Bs[ks + tig + 4][nb + g];
            }
#pragma unroll
            for (int i = 0; i < 2; i++)
#pragma unroll
                for (int j = 0; j < 4; j++)
                    MMA_TF32(c[i][j], a[i], b[j][0], b[j][1]);
        }
        __syncthreads();
    }

#pragma unroll
    for (int i = 0; i < 2; i++) {
        int r0 = row0 + wr0 + i * 16 + g;
#pragma unroll
        for (int j = 0; j < 4; j++) {
            int cc = col0 + wc0 + j * 8 + tig * 2;
#pragma unroll
            for (int h = 0; h < 2; h++) {
                int gr = r0 + h * 8;
                if (gr >= M) continue;
                float v0 = c[i][j][h * 2], v1 = c[i][j][h * 2 + 1];
                if (!SPLITK && bias) {
                    if (cc < N) v0 += bias[cc];
                    if (cc + 1 < N) v1 += bias[cc + 1];
                }
                if (RELU) { v0 = fmaxf(v0, 0.f); v1 = fmaxf(v1, 0.f); }
                if (cc + 1 < N) {
                    *(float2*)&C[(size_t)gr * N + cc] = make_float2(v0, v1);
                } else if (cc < N) {
                    C[(size_t)gr * N + cc] = v0;
                }
            }
        }
    }
}

// ---------------- split-K reduce for P and Q ----------------
__global__ void reduce_pq(const float* __restrict__ Pp, const float* __restrict__ Qp,
                          float* __restrict__ P, float* __restrict__ Q) {
    int idx = blockIdx.x * 256 + threadIdx.x;
    if (idx >= SQ * EMB) return;
    const float* src = blockIdx.y ? Qp : Pp;
    float* dst = blockIdx.y ? Q : P;
    float s = 0.f;
#pragma unroll
    for (int c = 0; c < NCH; c++) s += src[(size_t)c * SQ * EMB + idx];
    dst[idx] = s;
}

// ---------------- tensor-core flash attention (partials) ----------------
// grid (64, NCH, 6), block 128 = 4 warps x 16 queries
__global__ void attn_mma_kernel(const float* __restrict__ qkv_all,
                                float* __restrict__ part_o, float* __restrict__ part_ml) {
    __shared__ uint32_t k_s[TJ][104];     // tf32, [j][d] padded to 104
    __shared__ uint32_t v_s[TJ][104];
    __shared__ uint32_t p_s[4][16][36];   // per-warp P tile [q][j], stride 36

    int z = blockIdx.z, e = z / 3, h = z % 3;
    int qt = (int)gridDim.x - 1 - (int)blockIdx.x;  // heaviest first
    int q0 = qt * QB;
    int c = blockIdx.y, c0 = c * JCH;
    if (c0 > q0 + QB - 1) return;

    const float* qkv = qkv_all + (size_t)e * SQ * 900;
    int t = threadIdx.x, w = t >> 5, lane = t & 31;
    int g = lane >> 2, tig = lane & 3;

    int r0 = q0 + w * 16 + g;    // first q row of this thread
    int r1 = r0 + 8;             // second q row

    // Q fragments (rows r0/r1, cols d = ks*8 + tig(+4)), pre-scaled by 1/sqrt(HD)
    uint32_t qf[13][4];
    {
        const float* q0p = qkv + (size_t)r0 * 900 + h * HDIM;
        const float* q1p = qkv + (size_t)r1 * 900 + h * HDIM;
#pragma unroll
        for (int ks = 0; ks < 13; ks++) {
            int d0 = ks * 8 + tig;
            int d1 = d0 + 4;
            qf[ks][0] = f2tf(q0p[d0] * 0.1f);                       // d0 <= 99
            qf[ks][1] = f2tf(q1p[d0] * 0.1f);
            qf[ks][2] = f2tf(d1 < HDIM ? q0p[d1] * 0.1f : 0.f);
            qf[ks][3] = f2tf(d1 < HDIM ? q1p[d1] * 0.1f : 0.f);
        }
    }

    float of[13][4];
#pragma unroll
    for (int nt = 0; nt < 13; nt++) { of[nt][0] = of[nt][1] = of[nt][2] = of[nt][3] = 0.f; }
    float m0 = -INFINITY, m1 = -INFINITY, l0 = 0.f, l1 = 0.f;

    int jend = min(c0 + JCH, q0 + QB);
    for (int jt = c0; jt < jend; jt += TJ) {
        // stage K/V tile to smem (tf32), zero-pad d>=100
        for (int idx = t; idx < TJ * 104; idx += 128) {
            int row = idx / 104, col = idx - row * 104;
            const float* bp = qkv + (size_t)(jt + row) * 900 + h * HDIM + col;
            bool ok = col < HDIM;
            k_s[row][col] = f2tf(ok ? bp[300] : 0.f);
            v_s[row][col] = f2tf(ok ? bp[600] : 0.f);
        }
        __syncthreads();

        // S = Q K^T : 4 n-tiles of 8 j's
        float sc[4][4];
#pragma unroll
        for (int nt = 0; nt < 4; nt++) { sc[nt][0] = sc[nt][1] = sc[nt][2] = sc[nt][3] = 0.f; }
#pragma unroll
        for (int ks = 0; ks < 13; ks++) {
#pragma unroll
            for (int nt = 0; nt < 4; nt++) {
                uint32_t b0 = k_s[nt * 8 + g][ks * 8 + tig];
                uint32_t b1 = k_s[nt * 8 + g][ks * 8 + tig + 4];
                MMA_TF32(sc[nt], qf[ks], b0, b1);
            }
        }

        // causal mask (only diagonal steps need it)
        if (jt + TJ > q0) {
#pragma unroll
            for (int nt = 0; nt < 4; nt++) {
                int jb = jt + nt * 8 + 2 * tig;
                if (jb > r0)     sc[nt][0] = -INFINITY;
                if (jb + 1 > r0) sc[nt][1] = -INFINITY;
                if (jb > r1)     sc[nt][2] = -INFINITY;
                if (jb + 1 > r1) sc[nt][3] = -INFINITY;
            }
        }

        // online softmax (rows r0, r1), quad shfl reductions
        float rm0 = -INFINITY, rm1 = -INFINITY;
#pragma unroll
        for (int nt = 0; nt < 4; nt++) {
            rm0 = fmaxf(rm0, fmaxf(sc[nt][0], sc[nt][1]));
            rm1 = fmaxf(rm1, fmaxf(sc[nt][2], sc[nt][3]));
        }
        rm0 = fmaxf(rm0, __shfl_xor_sync(0xffffffffu, rm0, 1));
        rm0 = fmaxf(rm0, __shfl_xor_sync(0xffffffffu, rm0, 2));
        rm1 = fmaxf(rm1, __shfl_xor_sync(0xffffffffu, rm1, 1));
        rm1 = fmaxf(rm1, __shfl_xor_sync(0xffffffffu, rm1, 2));
        float mn0 = fmaxf(m0, rm0), mn1 = fmaxf(m1, rm1);
        float s0 = __expf(m0 - mn0), s1 = __expf(m1 - mn1);

        float rs0 = 0.f, rs1 = 0.f;
#pragma unroll
        for (int nt = 0; nt < 4; nt++) {
            float p0 = __expf(sc[nt][0] - mn0);
            float p1 = __expf(sc[nt][1] - mn0);
            float p2 = __expf(sc[nt][2] - mn1);
            float p3 = __expf(sc[nt][3] - mn1);
            rs0 += p0 + p1;
            rs1 += p2 + p3;
            int jc = nt * 8 + 2 * tig;
            p_s[w][g][jc]     = f2tf(p0);
            p_s[w][g][jc + 1] = f2tf(p1);
            p_s[w][g + 8][jc]     = f2tf(p2);
            p_s[w][g + 8][jc + 1] = f2tf(p3);
        }
        rs0 += __shfl_xor_sync(0xffffffffu, rs0, 1);
        rs0 += __shfl_xor_sync(0xffffffffu, rs0, 2);
        rs1 += __shfl_xor_sync(0xffffffffu, rs1, 1);
        rs1 += __shfl_xor_sync(0xffffffffu, rs1, 2);
        l0 = l0 * s0 + rs0;
        l1 = l1 * s1 + rs1;
        m0 = mn0; m1 = mn1;

        // rescale O
#pragma unroll
        for (int nt = 0; nt < 13; nt++) {
            of[nt][0] *= s0; of[nt][1] *= s0;
            of[nt][2] *= s1; of[nt][3] *= s1;
        }
        __syncwarp();

        // O += P V : 4 k-steps over j, 13 n-tiles over d
#pragma unroll
        for (int kj = 0; kj < 4; kj++) {
            uint32_t pa[4];
            pa[0] = p_s[w][g][kj * 8 + tig];
            pa[1] = p_s[w][g + 8][kj * 8 + tig];
            pa[2] = p_s[w][g][kj * 8 + tig + 4];
            pa[3] = p_s[w][g + 8][kj * 8 + tig + 4];
#pragma unroll
            for (int nt = 0; nt < 13; nt++) {
                uint32_t b0 = v_s[kj * 8 + tig][nt * 8 + g];
                uint32_t b1 = v_s[kj * 8 + tig + 4][nt * 8 + g];
                MMA_TF32(of[nt], pa, b0, b1);
            }
        }
        __syncthreads();
    }

    // write partials (unnormalized O + m,l)
    size_t pb0 = (size_t)(z * NCH + c) * SQ + r0;
    size_t pb1 = (size_t)(z * NCH + c) * SQ + r1;
#pragma unroll
    for (int nt = 0; nt < 13; nt++) {
        int d = nt * 8 + 2 * tig;
        if (d < HDIM) {
            *(float2*)&part_o[pb0 * HDIM + d] = make_float2(of[nt][0], of[nt][1]);
            *(float2*)&part_o[pb1 * HDIM + d] = make_float2(of[nt][2], of[nt][3]);
        }
    }
    if (tig == 0) {
        part_ml[pb0 * 2] = m0; part_ml[pb0 * 2 + 1] = l0;
        part_ml[pb1 * 2] = m1; part_ml[pb1 * 2 + 1] = l1;
    }
}

__global__ void attn_combine(const float* __restrict__ part_o,
                             const float* __restrict__ part_ml,
                             float* __restrict__ o_all) {
    int qi = blockIdx.x, h = blockIdx.y, e = blockIdx.z;
    int z = e * 3 + h;
    int t = threadIdx.x;
    int nch = qi / JCH + 1;
    float M = -INFINITY;
    for (int cc = 0; cc < nch; cc++)
        M = fmaxf(M, part_ml[((size_t)(z * NCH + cc) * SQ + qi) * 2]);
    float L = 0.f, acc = 0.f;
    for (int cc = 0; cc < nch; cc++) {
        size_t pb = (size_t)(z * NCH + cc) * SQ + qi;
        float w = __expf(part_ml[pb * 2] - M);
        L += part_ml[pb * 2 + 1] * w;
        if (t < HDIM) acc += w * part_o[pb * HDIM + t];
    }
    if (t < HDIM)
        o_all[((size_t)e * SQ + qi) * EMB + h * HDIM + t] = acc / L;
}

// ---------------- fused residual + LayerNorm ----------------
__global__ void ln_kernel(float* __restrict__ x, const float* __restrict__ delta,
                          const float* __restrict__ g, const float* __restrict__ b) {
    __shared__ float r1[128], r2[128];
    int z = blockIdx.z;
    x += (size_t)z * SQ * EMB; delta += (size_t)z * SQ * EMB;
    g += z * EMB; b += z * EMB;
    int r = blockIdx.x, t = threadIdx.x;
    float y[3];
    float s1 = 0.f, s2 = 0.f;
#pragma unroll
    for (int i = 0; i < 3; i++) {
        int c = t + i * 128;
        float v = 0.f;
        if (c < EMB) v = x[(size_t)r * EMB + c] + delta[(size_t)r * EMB + c];
        y[i] = v; s1 += v; s2 += v * v;
    }
    r1[t] = s1; r2[t] = s2;
    __syncthreads();
    for (int off = 64; off > 0; off >>= 1) {
        if (t < off) { r1[t] += r1[t + off]; r2[t] += r2[t + off]; }
        __syncthreads();
    }
    float mu = r1[0] / (float)EMB;
    float var = r2[0] / (float)EMB - mu * mu;
    float rstd = rsqrtf(var + 1e-5f);
#pragma unroll
    for (int i = 0; i < 3; i++) {
        int c = t + i * 128;
        if (c < EMB) x[(size_t)r * EMB + c] = (y[i] - mu) * rstd * g[c] + b[c];
    }
}

// ---------------- row softmax over A (in place) ----------------
__global__ void softmax_rows(float* __restrict__ A) {
    __shared__ float row[SQ];
    __shared__ float red[256];
    int r = blockIdx.x, t = threadIdx.x;
    float mx = -INFINITY;
    for (int j = t; j < SQ; j += 256) { float v = A[(size_t)r * SQ + j]; row[j] = v; mx = fmaxf(mx, v); }
    red[t] = mx; __syncthreads();
    for (int off = 128; off > 0; off >>= 1) { if (t < off) red[t] = fmaxf(red[t], red[t + off]); __syncthreads(); }
    mx = red[0];
    __syncthreads();
    float s = 0.f;
    for (int j = t; j < SQ; j += 256) { float e = __expf(row[j] - mx); row[j] = e; s += e; }
    red[t] = s; __syncthreads();
    for (int off = 128; off > 0; off >>= 1) { if (t < off) red[t] += red[t + off]; __syncthreads(); }
    float inv = 1.f / red[0];
    for (int j = t; j < SQ; j += 256) A[(size_t)r * SQ + j] = row[j] * inv;
}

// ---------------- column sum of elementwise max ----------------
__global__ void colsum_max_kernel(const float* __restrict__ X, const float* __restrict__ Y,
                                  float* __restrict__ out) {
    __shared__ float red[256];
    int c = blockIdx.x, t = threadIdx.x;
    float s = 0.f;
    for (int r = t; r < SQ; r += 256)
        s += fmaxf(X[(size_t)r * EMB + c], Y[(size_t)r * EMB + c]);
    red[t] = s; __syncthreads();
    for (int off = 128; off > 0; off >>= 1) { if (t < off) red[t] += red[t + off]; __syncthreads(); }
    if (t == 0) out[c] = red[0];
}

// ---------------- tiny FC layers ----------------
__global__ void fc1_kernel(const float* __restrict__ inp, const float* __restrict__ w,
                           const float* __restrict__ b, float* __restrict__ out) {
    __shared__ float red[128];
    int i = blockIdx.x, t = threadIdx.x;
    float s = 0.f;
    for (int j = t; j < 2 * EMB; j += 128) s += inp[j] * w[(size_t)i * 2 * EMB + j];
    red[t] = s; __syncthreads();
    for (int off = 64; off > 0; off >>= 1) { if (t < off) red[t] += red[t + off]; __syncthreads(); }
    if (t == 0) out[i] = fmaxf(red[0] + b[i], 0.f);
}

__global__ void fc2_kernel(const float* __restrict__ inp, const float* __restrict__ w,
                           const float* __restrict__ b, float* __restrict__ out) {
    __shared__ float red[256];
    int t = threadIdx.x;
    float s = 0.f;
    for (int j = t; j < EMB; j += 256) s += inp[j] * w[j];
    red[t] = s; __syncthreads();
    for (int off = 128; off > 0; off >>= 1) { if (t < off) red[t] += red[t + off]; __syncthreads(); }
    if (t == 0) out[0] = red[0] + b[0];
}

// ---------------- host orchestration ----------------
extern "C" void kernel_launch(void* const* d_in, const int* in_sizes, int n_in,
                              void* d_out, int out_size) {
    const float* solv = (const float*)d_in[0];
    const float* solu = (const float*)d_in[1];
    const float* ipw  = (const float*)d_in[2];
    const float* ipb  = (const float*)d_in[3];
    const float* ow   = (const float*)d_in[4];
    const float* ob   = (const float*)d_in[5];
    const float* g1   = (const float*)d_in[6];
    const float* b1   = (const float*)d_in[7];
    const float* w1   = (const float*)d_in[8];
    const float* bb1  = (const float*)d_in[9];
    const float* w2   = (const float*)d_in[10];
    const float* bb2  = (const float*)d_in[11];
    const float* g2   = (const float*)d_in[12];
    const float* b2   = (const float*)d_in[13];
    const float* fc1w = (const float*)d_in[14];
    const float* fc1b = (const float*)d_in[15];
    const float* fc2w = (const float*)d_in[16];
    const float* fc2b = (const float*)d_in[17];

    float *x, *qkv, *o, *t1, *ff, *A, *P, *Q, *Pp, *Qp, *po, *pml, *suv, *fc1o;
    cudaGetSymbolAddress((void**)&x,    g_x);
    cudaGetSymbolAddress((void**)&qkv,  g_qkv);
    cudaGetSymbolAddress((void**)&o,    g_o);
    cudaGetSymbolAddress((void**)&t1,   g_t1);
    cudaGetSymbolAddress((void**)&ff,   g_ff);
    cudaGetSymbolAddress((void**)&A,    g_A);
    cudaGetSymbolAddress((void**)&P,    g_P);
    cudaGetSymbolAddress((void**)&Q,    g_Q);
    cudaGetSymbolAddress((void**)&Pp,   g_Pp);
    cudaGetSymbolAddress((void**)&Qp,   g_Qp);
    cudaGetSymbolAddress((void**)&po,   g_part_o);
    cudaGetSymbolAddress((void**)&pml,  g_part_ml);
    cudaGetSymbolAddress((void**)&suv,  g_suv);
    cudaGetSymbolAddress((void**)&fc1o, g_fc1o);

    const size_t SE = (size_t)SQ * EMB;

    add_pe_kernel<<<dim3((SQ * EMB + 255) / 256, 1, 2), 256>>>(solv, solu, x);

    // qkv = x @ ipw^T + ipb
    mma_gemm<0, 1, 0, 0><<<dim3(15, 32, 2), 256>>>(
        x, ipw, ipb, qkv, SQ, 3 * EMB, EMB, EMB, EMB,
        SE, (size_t)3 * EMB * EMB, 3 * EMB, (size_t)SQ * 3 * EMB, 0);

    attn_mma_kernel<<<dim3(SQ / QB, NCH, 6), 128>>>(qkv, po, pml);
    attn_combine<<<dim3(SQ, NH, 2), 128>>>(po, pml, o);

    // proj = o @ ow^T + ob
    mma_gemm<0, 1, 0, 0><<<dim3(5, 32, 2), 256>>>(
        o, ow, ob, t1, SQ, EMB, EMB, EMB, EMB,
        SE, (size_t)EMB * EMB, EMB, SE, 0);
    ln_kernel<<<dim3(SQ, 1, 2), 128>>>(x, t1, g1, b1);

    // ff1 = relu(x @ w1^T + bb1)
    mma_gemm<0, 1, 1, 0><<<dim3(4, 32, 2), 256>>>(
        x, w1, bb1, ff, SQ, NHID, EMB, EMB, EMB,
        SE, (size_t)NHID * EMB, NHID, (size_t)SQ * NHID, 0);
    // ff2 = ff1 @ w2^T + bb2
    mma_gemm<0, 1, 0, 0><<<dim3(5, 32, 2), 256>>>(
        ff, w2, bb2, t1, SQ, EMB, NHID, NHID, NHID,
        (size_t)SQ * NHID, (size_t)EMB * NHID, EMB, SE, 0);
    ln_kernel<<<dim3(SQ, 1, 2), 128>>>(x, t1, g2, b2);

    float* H = x;
    float* G = x + SE;

    // A = H @ G^T
    mma_gemm<0, 1, 0, 0><<<dim3(64, 32, 1), 256>>>(
        H, G, (const float*)nullptr, A, SQ, SQ, EMB, EMB, EMB, 0, 0, 0, 0, 0);
    softmax_rows<<<SQ, 256>>>(A);

    // P = A @ G (NN, split-K x4), Q = A^T @ H (TN, split-K x4)
    mma_gemm<0, 0, 0, 1><<<dim3(5, 32, NCH), 256>>>(
        A, G, (const float*)nullptr, Pp, SQ, EMB, SQ, SQ, EMB, 0, 0, 0, SE, JCH);
    mma_gemm<1, 0, 0, 1><<<dim3(5, 32, NCH), 256>>>(
        A, H, (const float*)nullptr, Qp, SQ, EMB, SQ, SQ, EMB, 0, 0, 0, SE, JCH);
    reduce_pq<<<dim3((SQ * EMB + 255) / 256, 2), 256>>>(Pp, Qp, P, Q);

    colsum_max_kernel<<<EMB, 256>>>(H, P, suv);
    colsum_max_kernel<<<EMB, 256>>>(G, Q, suv + EMB);

    fc1_kernel<<<EMB, 128>>>(suv, fc1w, fc1b, fc1o);
    fc2_kernel<<<1, 256>>>(fc1o, fc2w, fc2b, (float*)d_out);
}

// round 5
// speedup vs baseline: 4.7944x; 1.7285x over previous
#include <cuda_runtime.h>
#include <math.h>
#include <stdint.h>

#define SQ   4096
#define EMB  300
#define NH   3
#define HDIM 100
#define NHID 200
#define QB   64
#define TJ   32
#define JCH  1024
#define NCH  4
#define KCF  64    // k floats per gemm tile
#define KPR  32    // packed pair-rows per tile
#define ASTR 136   // As smem stride (words)
#define BSTR 72    // Bs smem stride (words)

// ---------------- scratch (static device globals; no allocation) ----------------
__device__ float g_x[2 * SQ * EMB];
__device__ float g_qkv[2 * SQ * 3 * EMB];
__device__ float g_o[2 * SQ * EMB];
__device__ float g_t1[2 * SQ * EMB];
__device__ float g_ff[2 * SQ * NHID];
__device__ float g_A[SQ * SQ];
__device__ float g_P[SQ * EMB];
__device__ float g_Q[SQ * EMB];
__device__ float g_Pp[NCH * SQ * EMB];
__device__ float g_Qp[NCH * SQ * EMB];
__device__ float g_part_o[6 * NCH * SQ * HDIM];
__device__ float g_part_ml[6 * NCH * SQ * 2];
__device__ float g_suv[2 * EMB];
__device__ float g_fc1o[EMB];

// ---------------- positional encoding + add ----------------
__global__ void add_pe_kernel(const float* __restrict__ solv, const float* __restrict__ solu,
                              float* __restrict__ x) {
    int idx = blockIdx.x * blockDim.x + threadIdx.x;
    if (idx >= SQ * EMB) return;
    int z = blockIdx.z;
    const float* src = z ? solu : solv;
    int s = idx / EMB, c = idx % EMB;
    int k = c >> 1;
    float dv = expf(-(float)(2 * k) * (logf(10000.0f) / (float)EMB));
    float arg = (float)s * dv;
    float pe = (c & 1) ? cosf(arg) : sinf(arg);
    x[(size_t)z * SQ * EMB + idx] = src[idx] + pe;
}

// ---------------- bf16 helpers ----------------
// pack (lo=even-k, hi=odd-k) into one bf16x2 word
__device__ __forceinline__ uint32_t packbf(float lo, float hi) {
    uint32_t r;
    asm("cvt.rn.bf16x2.f32 %0, %1, %2;" : "=r"(r) : "f"(hi), "f"(lo));
    return r;
}

#define MMA_BF16(C, A, B0, B1)                                                  \
    asm volatile(                                                               \
        "mma.sync.aligned.m16n8k16.row.col.f32.bf16.bf16.f32 "                  \
        "{%0,%1,%2,%3},{%4,%5,%6,%7},{%8,%9},{%0,%1,%2,%3};"                    \
        : "+f"((C)[0]), "+f"((C)[1]), "+f"((C)[2]), "+f"((C)[3])                \
        : "r"((A)[0]), "r"((A)[1]), "r"((A)[2]), "r"((A)[3]), "r"(B0), "r"(B1))

// ---------------- bf16 tensor-core GEMM (128x64 tile, KCF=64, prefetch) ----------------
// C[m,n] = act( sum_k Ae(m,k)*Be(k,n) + bias[n] ),  ldc = N.   M must be mult of 128.
// Ae(m,k) = TA ? A[k*lda+m] : A[m*lda+k];  Be(k,n) = TB ? B[n*ldb+k] : B[k*ldb+n]
template<int TA, int TB, int RELU, int SPLITK>
__global__ __launch_bounds__(256, 2)
void mma_gemm(const float* __restrict__ A, const float* __restrict__ B,
              const float* __restrict__ bias, float* __restrict__ C,
              int M, int N, int K, int lda, int ldb,
              size_t sA, size_t sB, size_t sBias, size_t sC, int kc) {
    int z = blockIdx.z;
    int k_begin = 0, k_end = K;
    if (SPLITK) {
        k_begin = z * kc;
        k_end = min(K, k_begin + kc);
        C += (size_t)z * sC;
    } else {
        A += (size_t)z * sA; B += (size_t)z * sB; C += (size_t)z * sC;
        if (bias) bias += (size_t)z * sBias;
    }

    __shared__ uint32_t As[KPR][ASTR];
    __shared__ uint32_t Bs[KPR][BSTR];

    int t = threadIdx.x;
    int warp = t >> 5, lane = t & 31;
    int g = lane >> 2, tig = lane & 3;
    int wm = warp & 3, wn = warp >> 2;
    int row0 = blockIdx.y * 128, col0 = blockIdx.x * 64;
    int wr0 = wm * 32, wc0 = wn * 32;

    float acc[2][4][4];
#pragma unroll
    for (int i = 0; i < 2; i++)
#pragma unroll
        for (int j = 0; j < 4; j++)
#pragma unroll
            for (int h = 0; h < 4; h++) acc[i][j][h] = 0.f;

    uint32_t ra[16], rb[8];
    int nk = (k_end - k_begin + KCF - 1) / KCF;

    auto loadA = [&](int kt) {
        if (!TA) {
            int m = t >> 1, kq = (t & 1) * 32;
            const float* Ap = A + (size_t)(row0 + m) * lda + kt + kq;
            if (kt + kq + 31 < k_end) {
#pragma unroll
                for (int u = 0; u < 8; u++) {
                    float4 v = *(const float4*)(Ap + 4 * u);
                    ra[2 * u]     = packbf(v.x, v.y);
                    ra[2 * u + 1] = packbf(v.z, v.w);
                }
            } else {
#pragma unroll
                for (int u = 0; u < 16; u++) {
                    int gk = kt + kq + 2 * u;
                    float x0 = (gk < k_end) ? Ap[2 * u] : 0.f;
                    float x1 = (gk + 1 < k_end) ? Ap[2 * u + 1] : 0.f;
                    ra[u] = packbf(x0, x1);
                }
            }
        } else {
            int kp = t >> 3, mq = (t & 7) * 16;
            int gk0 = kt + 2 * kp;
            const float* Ap0 = A + (size_t)gk0 * lda + row0 + mq;
            bool ok0 = gk0 < k_end, ok1 = gk0 + 1 < k_end;
            if (ok0 && ok1) {
#pragma unroll
                for (int u = 0; u < 4; u++) {
                    float4 v0 = *(const float4*)(Ap0 + 4 * u);
                    float4 v1 = *(const float4*)(Ap0 + lda + 4 * u);
                    ra[4 * u]     = packbf(v0.x, v1.x);
                    ra[4 * u + 1] = packbf(v0.y, v1.y);
                    ra[4 * u + 2] = packbf(v0.z, v1.z);
                    ra[4 * u + 3] = packbf(v0.w, v1.w);
                }
            } else {
#pragma unroll
                for (int u = 0; u < 16; u++) {
                    float x0 = ok0 ? Ap0[u] : 0.f;
                    float x1 = ok1 ? Ap0[lda + u] : 0.f;
                    ra[u] = packbf(x0, x1);
                }
            }
        }
    };
    auto loadB = [&](int kt) {
        if (!TB) {
            int kp = t >> 3, nq = (t & 7) * 8;
            int gk0 = kt + 2 * kp;
            const float* Bp0 = B + (size_t)gk0 * ldb + col0 + nq;
            bool ok0 = gk0 < k_end, ok1 = gk0 + 1 < k_end;
            if (ok0 && ok1 && col0 + nq + 7 < N) {
#pragma unroll
                for (int u = 0; u < 2; u++) {
                    float4 v0 = *(const float4*)(Bp0 + 4 * u);
                    float4 v1 = *(const float4*)(Bp0 + ldb + 4 * u);
                    rb[4 * u]     = packbf(v0.x, v1.x);
                    rb[4 * u + 1] = packbf(v0.y, v1.y);
                    rb[4 * u + 2] = packbf(v0.z, v1.z);
                    rb[4 * u + 3] = packbf(v0.w, v1.w);
                }
            } else {
#pragma unroll
                for (int u = 0; u < 8; u++) {
                    bool okn = (col0 + nq + u) < N;
                    float x0 = (ok0 && okn) ? Bp0[u] : 0.f;
                    float x1 = (ok1 && okn) ? Bp0[ldb + u] : 0.f;
                    rb[u] = packbf(x0, x1);
                }
            }
        } else {
            int n = t >> 2, kq = (t & 3) * 16;
            int gn = col0 + n;
            const float* Bp = B + (size_t)gn * ldb + kt + kq;
            bool okn = gn < N;
            if (okn && kt + kq + 15 < k_end) {
#pragma unroll
                for (int u = 0; u < 4; u++) {
                    float4 v = *(const float4*)(Bp + 4 * u);
                    rb[2 * u]     = packbf(v.x, v.y);
                    rb[2 * u + 1] = packbf(v.z, v.w);
                }
            } else {
#pragma unroll
                for (int u = 0; u < 8; u++) {
                    int gk = kt + kq + 2 * u;
                    float x0 = (okn && gk < k_end) ? Bp[2 * u] : 0.f;
                    float x1 = (okn && gk + 1 < k_end) ? Bp[2 * u + 1] : 0.f;
                    rb[u] = packbf(x0, x1);
                }
            }
        }
    };

    loadA(k_begin); loadB(k_begin);
    for (int it = 0; it < nk; it++) {
        // store regs -> smem
        if (!TA) {
            int m = t >> 1, kp0 = (t & 1) * 16;
#pragma unroll
            for (int u = 0; u < 16; u++) As[kp0 + u][m] = ra[u];
        } else {
            int kp = t >> 3, mq = (t & 7) * 16;
#pragma unroll
            for (int u = 0; u < 16; u++) As[kp][mq + u] = ra[u];
        }
        if (!TB) {
            int kp = t >> 3, nq = (t & 7) * 8;
#pragma unroll
            for (int u = 0; u < 8; u++) Bs[kp][nq + u] = rb[u];
        } else {
            int n = t >> 2, kp0 = (t & 3) * 8;
#pragma unroll
            for (int u = 0; u < 8; u++) Bs[kp0 + u][n] = rb[u];
        }
        __syncthreads();
        if (it + 1 < nk) { loadA(k_begin + (it + 1) * KCF); loadB(k_begin + (it + 1) * KCF); }
#pragma unroll
        for (int ks = 0; ks < KPR; ks += 8) {
            uint32_t a[2][4], b[4][2];
#pragma unroll
            for (int i = 0; i < 2; i++) {
                int mb = wr0 + i * 16;
                a[i][0] = As[ks + tig][mb + g];
                a[i][1] = As[ks + tig][mb + 8 + g];
                a[i][2] = As[ks + tig + 4][mb + g];
                a[i][3] = As[ks + tig + 4][mb + 8 + g];
            }
#pragma unroll
            for (int j = 0; j < 4; j++) {
                int nb = wc0 + j * 8;
                b[j][0] = Bs[ks + tig][nb + g];
                b[j][1] = Bs[ks + tig + 4][nb + g];
            }
#pragma unroll
            for (int i = 0; i < 2; i++)
#pragma unroll
                for (int j = 0; j < 4; j++)
                    MMA_BF16(acc[i][j], a[i], b[j][0], b[j][1]);
        }
        __syncthreads();
    }

#pragma unroll
    for (int i = 0; i < 2; i++) {
        int r0 = row0 + wr0 + i * 16 + g;
#pragma unroll
        for (int j = 0; j < 4; j++) {
            int cc = col0 + wc0 + j * 8 + tig * 2;
#pragma unroll
            for (int h = 0; h < 2; h++) {
                int gr = r0 + h * 8;
                float v0 = acc[i][j][h * 2], v1 = acc[i][j][h * 2 + 1];
                if (!SPLITK && bias) {
                    if (cc < N) v0 += bias[cc];
                    if (cc + 1 < N) v1 += bias[cc + 1];
                }
                if (RELU) { v0 = fmaxf(v0, 0.f); v1 = fmaxf(v1, 0.f); }
                if (cc + 1 < N) {
                    *(float2*)&C[(size_t)gr * N + cc] = make_float2(v0, v1);
                } else if (cc < N) {
                    C[(size_t)gr * N + cc] = v0;
                }
            }
        }
    }
}

// ---------------- split-K reduce for P and Q ----------------
__global__ void reduce_pq(const float* __restrict__ Pp, const float* __restrict__ Qp,
                          float* __restrict__ P, float* __restrict__ Q) {
    int idx = blockIdx.x * 256 + threadIdx.x;
    if (idx >= SQ * EMB) return;
    const float* src = blockIdx.y ? Qp : Pp;
    float* dst = blockIdx.y ? Q : P;
    float s = 0.f;
#pragma unroll
    for (int c = 0; c < NCH; c++) s += src[(size_t)c * SQ * EMB + idx];
    dst[idx] = s;
}

// ---------------- bf16 tensor-core flash attention (partials) ----------------
// grid (64, NCH, 6), block 128 = 4 warps x 16 queries
__global__ void attn_mma_kernel(const float* __restrict__ qkv_all,
                                float* __restrict__ part_o, float* __restrict__ part_ml) {
    __shared__ uint32_t k_s[TJ][60];      // K packed along d: [j][d-pair], 56 used
    __shared__ uint32_t v_s[16][108];     // V packed along j: [j-pair][d], 104 used
    __shared__ uint32_t p_s[4][16][20];   // per-warp P: [q-row][j-pair], 16 used

    int z = blockIdx.z, e = z / 3, h = z % 3;
    int qt = (int)gridDim.x - 1 - (int)blockIdx.x;  // heaviest first
    int q0 = qt * QB;
    int c = blockIdx.y, c0 = c * JCH;
    if (c0 > q0 + QB - 1) return;

    const float* qkv = qkv_all + (size_t)e * SQ * 900;
    int t = threadIdx.x, w = t >> 5, lane = t & 31;
    int g = lane >> 2, tig = lane & 3;

    int r0 = q0 + w * 16 + g;
    int r1 = r0 + 8;

    // Q fragments (bf16x2 packed along d), pre-scaled by 1/sqrt(HD)
    uint32_t qf[7][4];
    {
        const float* q0p = qkv + (size_t)r0 * 900 + h * HDIM;
        const float* q1p = qkv + (size_t)r1 * 900 + h * HDIM;
#pragma unroll
        for (int s = 0; s < 7; s++) {
            int d0 = 2 * (s * 8 + tig);
            int d1 = 2 * (s * 8 + tig + 4);
            float a0 = d0 < HDIM ? q0p[d0] * 0.1f : 0.f;
            float a1 = d0 + 1 < HDIM ? q0p[d0 + 1] * 0.1f : 0.f;
            float b0 = d0 < HDIM ? q1p[d0] * 0.1f : 0.f;
            float b1 = d0 + 1 < HDIM ? q1p[d0 + 1] * 0.1f : 0.f;
            float c0f = d1 < HDIM ? q0p[d1] * 0.1f : 0.f;
            float c1f = d1 + 1 < HDIM ? q0p[d1 + 1] * 0.1f : 0.f;
            float e0 = d1 < HDIM ? q1p[d1] * 0.1f : 0.f;
            float e1 = d1 + 1 < HDIM ? q1p[d1 + 1] * 0.1f : 0.f;
            qf[s][0] = packbf(a0, a1);
            qf[s][1] = packbf(b0, b1);
            qf[s][2] = packbf(c0f, c1f);
            qf[s][3] = packbf(e0, e1);
        }
    }

    float of[13][4];
#pragma unroll
    for (int nt = 0; nt < 13; nt++) { of[nt][0] = of[nt][1] = of[nt][2] = of[nt][3] = 0.f; }
    float m0 = -INFINITY, m1 = -INFINITY, l0 = 0.f, l1 = 0.f;

    int jend = min(c0 + JCH, q0 + QB);
    for (int jt = c0; jt < jend; jt += TJ) {
        // stage K (packed along d)
        for (int idx = t; idx < TJ * 56; idx += 128) {
            int row = idx / 56, dp = idx - row * 56;
            int d0 = 2 * dp;
            const float* kp = qkv + (size_t)(jt + row) * 900 + h * HDIM + 300;
            float x0 = d0 < HDIM ? kp[d0] : 0.f;       // d0<100 implies d0+1<=99
            float x1 = d0 < HDIM ? kp[d0 + 1] : 0.f;
            k_s[row][dp] = packbf(x0, x1);
        }
        // stage V (packed along j)
        for (int idx = t; idx < 16 * 104; idx += 128) {
            int jp = idx / 104, d = idx - jp * 104;
            const float* vp = qkv + (size_t)(jt + 2 * jp) * 900 + h * HDIM + 600 + d;
            float x0 = d < HDIM ? vp[0] : 0.f;
            float x1 = d < HDIM ? vp[900] : 0.f;
            v_s[jp][d] = packbf(x0, x1);
        }
        __syncthreads();

        // S = Q K^T
        float sc[4][4];
#pragma unroll
        for (int nt = 0; nt < 4; nt++) { sc[nt][0] = sc[nt][1] = sc[nt][2] = sc[nt][3] = 0.f; }
#pragma unroll
        for (int s = 0; s < 7; s++) {
#pragma unroll
            for (int nt = 0; nt < 4; nt++) {
                uint32_t b0 = k_s[nt * 8 + g][s * 8 + tig];
                uint32_t b1 = k_s[nt * 8 + g][s * 8 + tig + 4];
                MMA_BF16(sc[nt], qf[s], b0, b1);
            }
        }

        // causal mask (diagonal steps only)
        if (jt + TJ > q0) {
#pragma unroll
            for (int nt = 0; nt < 4; nt++) {
                int jb = jt + nt * 8 + 2 * tig;
                if (jb > r0)     sc[nt][0] = -INFINITY;
                if (jb + 1 > r0) sc[nt][1] = -INFINITY;
                if (jb > r1)     sc[nt][2] = -INFINITY;
                if (jb + 1 > r1) sc[nt][3] = -INFINITY;
            }
        }

        // online softmax
        float rm0 = -INFINITY, rm1 = -INFINITY;
#pragma unroll
        for (int nt = 0; nt < 4; nt++) {
            rm0 = fmaxf(rm0, fmaxf(sc[nt][0], sc[nt][1]));
            rm1 = fmaxf(rm1, fmaxf(sc[nt][2], sc[nt][3]));
        }
        rm0 = fmaxf(rm0, __shfl_xor_sync(0xffffffffu, rm0, 1));
        rm0 = fmaxf(rm0, __shfl_xor_sync(0xffffffffu, rm0, 2));
        rm1 = fmaxf(rm1, __shfl_xor_sync(0xffffffffu, rm1, 1));
        rm1 = fmaxf(rm1, __shfl_xor_sync(0xffffffffu, rm1, 2));
        float mn0 = fmaxf(m0, rm0), mn1 = fmaxf(m1, rm1);
        float s0 = __expf(m0 - mn0), s1 = __expf(m1 - mn1);

        float rs0 = 0.f, rs1 = 0.f;
#pragma unroll
        for (int nt = 0; nt < 4; nt++) {
            float p0 = __expf(sc[nt][0] - mn0);
            float p1 = __expf(sc[nt][1] - mn0);
            float p2 = __expf(sc[nt][2] - mn1);
            float p3 = __expf(sc[nt][3] - mn1);
            rs0 += p0 + p1;
            rs1 += p2 + p3;
            p_s[w][g][nt * 4 + tig]     = packbf(p0, p1);
            p_s[w][g + 8][nt * 4 + tig] = packbf(p2, p3);
        }
        rs0 += __shfl_xor_sync(0xffffffffu, rs0, 1);
        rs0 += __shfl_xor_sync(0xffffffffu, rs0, 2);
        rs1 += __shfl_xor_sync(0xffffffffu, rs1, 1);
        rs1 += __shfl_xor_sync(0xffffffffu, rs1, 2);
        l0 = l0 * s0 + rs0;
        l1 = l1 * s1 + rs1;
        m0 = mn0; m1 = mn1;

#pragma unroll
        for (int nt = 0; nt < 13; nt++) {
            of[nt][0] *= s0; of[nt][1] *= s0;
            of[nt][2] *= s1; of[nt][3] *= s1;
        }
        __syncwarp();

        // O += P V (k over j: 2 ksteps of 8 j-pairs)
#pragma unroll
        for (int ks = 0; ks < 16; ks += 8) {
            uint32_t pa[4];
            pa[0] = p_s[w][g][ks + tig];
            pa[1] = p_s[w][g + 8][ks + tig];
            pa[2] = p_s[w][g][ks + tig + 4];
            pa[3] = p_s[w][g + 8][ks + tig + 4];
#pragma unroll
            for (int nt = 0; nt < 13; nt++) {
                uint32_t b0 = v_s[ks + tig][nt * 8 + g];
                uint32_t b1 = v_s[ks + tig + 4][nt * 8 + g];
                MMA_BF16(of[nt], pa, b0, b1);
            }
        }
        __syncthreads();
    }

    // write partials
    size_t pb0 = (size_t)(z * NCH + c) * SQ + r0;
    size_t pb1 = (size_t)(z * NCH + c) * SQ + r1;
#pragma unroll
    for (int nt = 0; nt < 13; nt++) {
        int d = nt * 8 + 2 * tig;
        if (d < HDIM) {
            *(float2*)&part_o[pb0 * HDIM + d] = make_float2(of[nt][0], of[nt][1]);
            *(float2*)&part_o[pb1 * HDIM + d] = make_float2(of[nt][2], of[nt][3]);
        }
    }
    if (tig == 0) {
        part_ml[pb0 * 2] = m0; part_ml[pb0 * 2 + 1] = l0;
        part_ml[pb1 * 2] = m1; part_ml[pb1 * 2 + 1] = l1;
    }
}

__global__ void attn_combine(const float* __restrict__ part_o,
                             const float* __restrict__ part_ml,
                             float* __restrict__ o_all) {
    int qi = blockIdx.x, h = blockIdx.y, e = blockIdx.z;
    int z = e * 3 + h;
    int t = threadIdx.x;
    int nch = qi / JCH + 1;
    float M = -INFINITY;
    for (int cc = 0; cc < nch; cc++)
        M = fmaxf(M, part_ml[((size_t)(z * NCH + cc) * SQ + qi) * 2]);
    float L = 0.f, acc = 0.f;
    for (int cc = 0; cc < nch; cc++) {
        size_t pb = (size_t)(z * NCH + cc) * SQ + qi;
        float w = __expf(part_ml[pb * 2] - M);
        L += part_ml[pb * 2 + 1] * w;
        if (t < HDIM) acc += w * part_o[pb * HDIM + t];
    }
    if (t < HDIM)
        o_all[((size_t)e * SQ + qi) * EMB + h * HDIM + t] = acc / L;
}

// ---------------- fused residual + LayerNorm ----------------
__global__ void ln_kernel(float* __restrict__ x, const float* __restrict__ delta,
                          const float* __restrict__ g, const float* __restrict__ b) {
    __shared__ float r1[128], r2[128];
    int z = blockIdx.z;
    x += (size_t)z * SQ * EMB; delta += (size_t)z * SQ * EMB;
    g += z * EMB; b += z * EMB;
    int r = blockIdx.x, t = threadIdx.x;
    float y[3];
    float s1 = 0.f, s2 = 0.f;
#pragma unroll
    for (int i = 0; i < 3; i++) {
        int c = t + i * 128;
        float v = 0.f;
        if (c < EMB) v = x[(size_t)r * EMB + c] + delta[(size_t)r * EMB + c];
        y[i] = v; s1 += v; s2 += v * v;
    }
    r1[t] = s1; r2[t] = s2;
    __syncthreads();
    for (int off = 64; off > 0; off >>= 1) {
        if (t < off) { r1[t] += r1[t + off]; r2[t] += r2[t + off]; }
        __syncthreads();
    }
    float mu = r1[0] / (float)EMB;
    float var = r2[0] / (float)EMB - mu * mu;
    float rstd = rsqrtf(var + 1e-5f);
#pragma unroll
    for (int i = 0; i < 3; i++) {
        int c = t + i * 128;
        if (c < EMB) x[(size_t)r * EMB + c] = (y[i] - mu) * rstd * g[c] + b[c];
    }
}

// ---------------- row softmax over A (in place) ----------------
__global__ void softmax_rows(float* __restrict__ A) {
    __shared__ float row[SQ];
    __shared__ float red[256];
    int r = blockIdx.x, t = threadIdx.x;
    float mx = -INFINITY;
    for (int j = t; j < SQ; j += 256) { float v = A[(size_t)r * SQ + j]; row[j] = v; mx = fmaxf(mx, v); }
    red[t] = mx; __syncthreads();
    for (int off = 128; off > 0; off >>= 1) { if (t < off) red[t] = fmaxf(red[t], red[t + off]); __syncthreads(); }
    mx = red[0];
    __syncthreads();
    float s = 0.f;
    for (int j = t; j < SQ; j += 256) { float e = __expf(row[j] - mx); row[j] = e; s += e; }
    red[t] = s; __syncthreads();
    for (int off = 128; off > 0; off >>= 1) { if (t < off) red[t] += red[t + off]; __syncthreads(); }
    float inv = 1.f / red[0];
    for (int j = t; j < SQ; j += 256) A[(size_t)r * SQ + j] = row[j] * inv;
}

// ---------------- column sum of elementwise max ----------------
__global__ void colsum_max_kernel(const float* __restrict__ X, const float* __restrict__ Y,
                                  float* __restrict__ out) {
    __shared__ float red[256];
    int c = blockIdx.x, t = threadIdx.x;
    float s = 0.f;
    for (int r = t; r < SQ; r += 256)
        s += fmaxf(X[(size_t)r * EMB + c], Y[(size_t)r * EMB + c]);
    red[t] = s; __syncthreads();
    for (int off = 128; off > 0; off >>= 1) { if (t < off) red[t] += red[t + off]; __syncthreads(); }
    if (t == 0) out[c] = red[0];
}

// ---------------- tiny FC layers ----------------
__global__ void fc1_kernel(const float* __restrict__ inp, const float* __restrict__ w,
                           const float* __restrict__ b, float* __restrict__ out) {
    __shared__ float red[128];
    int i = blockIdx.x, t = threadIdx.x;
    float s = 0.f;
    for (int j = t; j < 2 * EMB; j += 128) s += inp[j] * w[(size_t)i * 2 * EMB + j];
    red[t] = s; __syncthreads();
    for (int off = 64; off > 0; off >>= 1) { if (t < off) red[t] += red[t + off]; __syncthreads(); }
    if (t == 0) out[i] = fmaxf(red[0] + b[i], 0.f);
}

__global__ void fc2_kernel(const float* __restrict__ inp, const float* __restrict__ w,
                           const float* __restrict__ b, float* __restrict__ out) {
    __shared__ float red[256];
    int t = threadIdx.x;
    float s = 0.f;
    for (int j = t; j < EMB; j += 256) s += inp[j] * w[j];
    red[t] = s; __syncthreads();
    for (int off = 128; off > 0; off >>= 1) { if (t < off) red[t] += red[t + off]; __syncthreads(); }
    if (t == 0) out[0] = red[0] + b[0];
}

// ---------------- host orchestration ----------------
extern "C" void kernel_launch(void* const* d_in, const int* in_sizes, int n_in,
                              void* d_out, int out_size) {
    const float* solv = (const float*)d_in[0];
    const float* solu = (const float*)d_in[1];
    const float* ipw  = (const float*)d_in[2];
    const float* ipb  = (const float*)d_in[3];
    const float* ow   = (const float*)d_in[4];
    const float* ob   = (const float*)d_in[5];
    const float* g1   = (const float*)d_in[6];
    const float* b1   = (const float*)d_in[7];
    const float* w1   = (const float*)d_in[8];
    const float* bb1  = (const float*)d_in[9];
    const float* w2   = (const float*)d_in[10];
    const float* bb2  = (const float*)d_in[11];
    const float* g2   = (const float*)d_in[12];
    const float* b2   = (const float*)d_in[13];
    const float* fc1w = (const float*)d_in[14];
    const float* fc1b = (const float*)d_in[15];
    const float* fc2w = (const float*)d_in[16];
    const float* fc2b = (const float*)d_in[17];

    float *x, *qkv, *o, *t1, *ff, *A, *P, *Q, *Pp, *Qp, *po, *pml, *suv, *fc1o;
    cudaGetSymbolAddress((void**)&x,    g_x);
    cudaGetSymbolAddress((void**)&qkv,  g_qkv);
    cudaGetSymbolAddress((void**)&o,    g_o);
    cudaGetSymbolAddress((void**)&t1,   g_t1);
    cudaGetSymbolAddress((void**)&ff,   g_ff);
    cudaGetSymbolAddress((void**)&A,    g_A);
    cudaGetSymbolAddress((void**)&P,    g_P);
    cudaGetSymbolAddress((void**)&Q,    g_Q);
    cudaGetSymbolAddress((void**)&Pp,   g_Pp);
    cudaGetSymbolAddress((void**)&Qp,   g_Qp);
    cudaGetSymbolAddress((void**)&po,   g_part_o);
    cudaGetSymbolAddress((void**)&pml,  g_part_ml);
    cudaGetSymbolAddress((void**)&suv,  g_suv);
    cudaGetSymbolAddress((void**)&fc1o, g_fc1o);

    const size_t SE = (size_t)SQ * EMB;

    add_pe_kernel<<<dim3((SQ * EMB + 255) / 256, 1, 2), 256>>>(solv, solu, x);

    // qkv = x @ ipw^T + ipb
    mma_gemm<0, 1, 0, 0><<<dim3(15, 32, 2), 256>>>(
        x, ipw, ipb, qkv, SQ, 3 * EMB, EMB, EMB, EMB,
        SE, (size_t)3 * EMB * EMB, 3 * EMB, (size_t)SQ * 3 * EMB, 0);

    attn_mma_kernel<<<dim3(SQ / QB, NCH, 6), 128>>>(qkv, po, pml);
    attn_combine<<<dim3(SQ, NH, 2), 128>>>(po, pml, o);

    // proj = o @ ow^T + ob
    mma_gemm<0, 1, 0, 0><<<dim3(5, 32, 2), 256>>>(
        o, ow, ob, t1, SQ, EMB, EMB, EMB, EMB,
        SE, (size_t)EMB * EMB, EMB, SE, 0);
    ln_kernel<<<dim3(SQ, 1, 2), 128>>>(x, t1, g1, b1);

    // ff1 = relu(x @ w1^T + bb1)
    mma_gemm<0, 1, 1, 0><<<dim3(4, 32, 2), 256>>>(
        x, w1, bb1, ff, SQ, NHID, EMB, EMB, EMB,
        SE, (size_t)NHID * EMB, NHID, (size_t)SQ * NHID, 0);
    // ff2 = ff1 @ w2^T + bb2
    mma_gemm<0, 1, 0, 0><<<dim3(5, 32, 2), 256>>>(
        ff, w2, bb2, t1, SQ, EMB, NHID, NHID, NHID,
        (size_t)SQ * NHID, (size_t)EMB * NHID, EMB, SE, 0);
    ln_kernel<<<dim3(SQ, 1, 2), 128>>>(x, t1, g2, b2);

    float* H = x;
    float* G = x + SE;

    // A = H @ G^T
    mma_gemm<0, 1, 0, 0><<<dim3(64, 32, 1), 256>>>(
        H, G, (const float*)nullptr, A, SQ, SQ, EMB, EMB, EMB, 0, 0, 0, 0, 0);
    softmax_rows<<<SQ, 256>>>(A);

    // P = A @ G (NN, split-K x4), Q = A^T @ H (TN, split-K x4)
    mma_gemm<0, 0, 0, 1><<<dim3(5, 32, NCH), 256>>>(
        A, G, (const float*)nullptr, Pp, SQ, EMB, SQ, SQ, EMB, 0, 0, 0, SE, JCH);
    mma_gemm<1, 0, 0, 1><<<dim3(5, 32, NCH), 256>>>(
        A, H, (const float*)nullptr, Qp, SQ, EMB, SQ, SQ, EMB, 0, 0, 0, SE, JCH);
    reduce_pq<<<dim3((SQ * EMB + 255) / 256, 2), 256>>>(Pp, Qp, P, Q);

    colsum_max_kernel<<<EMB, 256>>>(H, P, suv);
    colsum_max_kernel<<<EMB, 256>>>(G, Q, suv + EMB);

    fc1_kernel<<<EMB, 128>>>(suv, fc1w, fc1b, fc1o);
    fc2_kernel<<<1, 256>>>(fc1o, fc2w, fc2b, (float*)d_out);
}